// round 1
// baseline (speedup 1.0000x reference)
#include <cuda_runtime.h>
#include <cuda_bf16.h>
#include <math.h>

// Problem constants
#define TOK   4096          // B*N = 2*2048
#define EMB   1024
#define NH    16
#define HD    64
#define SEQ   2048
#define MLP   4096
#define LN_EPS 1e-5f

// ---------------- scratch (device globals; no allocs allowed) ----------------
static __device__ float g_h  [(size_t)TOK * EMB];        // LN output (reused)
static __device__ float g_qkv[(size_t)TOK * 3 * EMB];    // QKV
static __device__ float g_o  [(size_t)TOK * EMB];        // attention output
static __device__ float g_x1 [(size_t)TOK * EMB];        // post-attn residual
static __device__ float g_act[(size_t)TOK * MLP];        // GELU(fc1)

// ---------------- LayerNorm: one block per row ----------------
__global__ void ln_kernel(const float* __restrict__ in, float* __restrict__ out,
                          const float* __restrict__ gam, const float* __restrict__ bet)
{
    __shared__ float red[32];
    __shared__ float s_mu, s_rstd;
    const int row = blockIdx.x;
    const float* x = in + (size_t)row * EMB;
    float* y = out + (size_t)row * EMB;
    const int tid = threadIdx.x;   // 256 threads

    float v[4];
    float s = 0.f, sq = 0.f;
#pragma unroll
    for (int i = 0; i < 4; ++i) {
        v[i] = x[tid + i * 256];
        s  += v[i];
        sq += v[i] * v[i];
    }
    // block reduce (sum of s and sq)
    const unsigned FULL = 0xffffffffu;
#pragma unroll
    for (int o = 16; o > 0; o >>= 1) {
        s  += __shfl_down_sync(FULL, s,  o);
        sq += __shfl_down_sync(FULL, sq, o);
    }
    int warp = tid >> 5, lane = tid & 31;
    __shared__ float red2[32];
    if (lane == 0) { red[warp] = s; red2[warp] = sq; }
    __syncthreads();
    if (warp == 0) {
        s  = (lane < 8) ? red[lane]  : 0.f;
        sq = (lane < 8) ? red2[lane] : 0.f;
#pragma unroll
        for (int o = 4; o > 0; o >>= 1) {
            s  += __shfl_down_sync(FULL, s,  o);
            sq += __shfl_down_sync(FULL, sq, o);
        }
        if (lane == 0) {
            float mu  = s * (1.f / EMB);
            float var = sq * (1.f / EMB) - mu * mu;
            s_mu = mu;
            s_rstd = rsqrtf(var + LN_EPS);
        }
    }
    __syncthreads();
    float mu = s_mu, rstd = s_rstd;
#pragma unroll
    for (int i = 0; i < 4; ++i) {
        int c = tid + i * 256;
        y[c] = (v[i] - mu) * rstd * gam[c] + bet[c];
    }
}

// ---------------- GEMM: C[M,N] = act(A[M,K] @ B[K,N] + bias) (+ res) ----------------
__device__ __forceinline__ float gelu_exact(float x)
{
    return 0.5f * x * (1.f + erff(x * 0.70710678118654752f));
}

template<bool GELU, bool RES>
__global__ void __launch_bounds__(256, 2)
gemm_kernel(const float* __restrict__ A, const float* __restrict__ B,
            const float* __restrict__ bias, const float* __restrict__ res,
            float* __restrict__ C, int M, int N, int K)
{
    __shared__ float As[8][128];
    __shared__ float Bs[8][128];

    const int tid = threadIdx.x;          // 256 threads
    const int bm = blockIdx.y * 128;
    const int bn = blockIdx.x * 128;
    const int tx = tid & 15;              // 0..15
    const int ty = tid >> 4;              // 0..15

    // global-load mapping
    const int arow = tid >> 1;            // 0..127
    const int acol = (tid & 1) * 4;       // 0 or 4
    const int brow = tid >> 5;            // 0..7
    const int bcol = (tid & 31) * 4;      // 0..124

    const float* Aptr = A + (size_t)(bm + arow) * K + acol;
    const float* Bptr = B + (size_t)brow * N + bn + bcol;

    float acc[8][8];
#pragma unroll
    for (int i = 0; i < 8; ++i)
#pragma unroll
        for (int j = 0; j < 8; ++j) acc[i][j] = 0.f;

    for (int k0 = 0; k0 < K; k0 += 8) {
        float4 av = *(const float4*)(Aptr + k0);
        float4 bv = *(const float4*)(Bptr + (size_t)k0 * N);
        __syncthreads();
        As[acol + 0][arow] = av.x;
        As[acol + 1][arow] = av.y;
        As[acol + 2][arow] = av.z;
        As[acol + 3][arow] = av.w;
        *(float4*)&Bs[brow][bcol] = bv;
        __syncthreads();

#pragma unroll
        for (int k = 0; k < 8; ++k) {
            float a[8], b[8];
            *(float4*)(a)     = *(const float4*)&As[k][ty * 8];
            *(float4*)(a + 4) = *(const float4*)&As[k][ty * 8 + 4];
            *(float4*)(b)     = *(const float4*)&Bs[k][tx * 8];
            *(float4*)(b + 4) = *(const float4*)&Bs[k][tx * 8 + 4];
#pragma unroll
            for (int i = 0; i < 8; ++i)
#pragma unroll
                for (int j = 0; j < 8; ++j)
                    acc[i][j] = fmaf(a[i], b[j], acc[i][j]);
        }
    }

    // epilogue
#pragma unroll
    for (int i = 0; i < 8; ++i) {
        int gm = bm + ty * 8 + i;
#pragma unroll
        for (int j = 0; j < 8; ++j) {
            int gn = bn + tx * 8 + j;
            float v = acc[i][j] + bias[gn];
            if (GELU) v = gelu_exact(v);
            if (RES)  v += res[(size_t)gm * N + gn];
            C[(size_t)gm * N + gn] = v;
        }
    }
}

// ---------------- Attention: one block per (b,h,query row) ----------------
__global__ void __launch_bounds__(128)
attn_kernel(const float* __restrict__ qkv, float* __restrict__ o)
{
    __shared__ float q[HD];
    __shared__ float sc[SEQ];
    __shared__ float red[32];
    __shared__ float part[128];
    __shared__ float s_max, s_inv;

    const int bh = blockIdx.x;        // 0..31
    const int n  = blockIdx.y;        // 0..2047
    const int b  = bh >> 4;
    const int h  = bh & 15;
    const int tid = threadIdx.x;      // 128 threads
    const unsigned FULL = 0xffffffffu;

    const size_t rowstride = 3 * EMB;
    const size_t tbase = (size_t)b * SEQ;
    const float scale = 0.125f;       // 1/sqrt(64)

    // load q (pre-scaled)
    if (tid < HD)
        q[tid] = qkv[(tbase + n) * rowstride + h * HD + tid] * scale;
    __syncthreads();

    // ---- scores + max ----
    float lmax = -INFINITY;
    for (int j = tid; j < SEQ; j += 128) {
        const float4* k4 = (const float4*)(qkv + (tbase + j) * rowstride + EMB + h * HD);
        const float4* q4 = (const float4*)q;
        float dot = 0.f;
#pragma unroll
        for (int d = 0; d < HD / 4; ++d) {
            float4 kk = k4[d];
            float4 qq = q4[d];
            dot += qq.x * kk.x + qq.y * kk.y + qq.z * kk.z + qq.w * kk.w;
        }
        sc[j] = dot;
        lmax = fmaxf(lmax, dot);
    }
    // block-reduce max
#pragma unroll
    for (int off = 16; off > 0; off >>= 1)
        lmax = fmaxf(lmax, __shfl_down_sync(FULL, lmax, off));
    {
        int warp = tid >> 5, lane = tid & 31;
        if (lane == 0) red[warp] = lmax;
        __syncthreads();
        if (warp == 0) {
            float v = (lane < 4) ? red[lane] : -INFINITY;
#pragma unroll
            for (int off = 2; off > 0; off >>= 1)
                v = fmaxf(v, __shfl_down_sync(FULL, v, off));
            if (lane == 0) s_max = v;
        }
        __syncthreads();
    }
    const float bmax = s_max;

    // ---- exp + sum ----
    float lsum = 0.f;
    for (int j = tid; j < SEQ; j += 128) {
        float e = expf(sc[j] - bmax);
        sc[j] = e;
        lsum += e;
    }
#pragma unroll
    for (int off = 16; off > 0; off >>= 1)
        lsum += __shfl_down_sync(FULL, lsum, off);
    {
        int warp = tid >> 5, lane = tid & 31;
        __syncthreads();               // red[] reuse guard
        if (lane == 0) red[warp] = lsum;
        __syncthreads();
        if (warp == 0) {
            float v = (lane < 4) ? red[lane] : 0.f;
#pragma unroll
            for (int off = 2; off > 0; off >>= 1)
                v += __shfl_down_sync(FULL, v, off);
            if (lane == 0) s_inv = 1.f / v;
        }
        __syncthreads();
    }
    const float inv = s_inv;

    // ---- AV: 2 halves of the key range x 64 head dims ----
    const int half = tid >> 6;   // 0 or 1
    const int d    = tid & 63;
    float acc = 0.f;
    const int j0 = half * (SEQ / 2);
    const float* vbase = qkv + (tbase + j0) * rowstride + 2 * EMB + h * HD + d;
#pragma unroll 4
    for (int j = 0; j < SEQ / 2; ++j)
        acc = fmaf(sc[j0 + j], vbase[(size_t)j * rowstride], acc);
    part[tid] = acc;
    __syncthreads();
    if (tid < HD)
        o[(tbase + n) * EMB + h * HD + tid] = (part[tid] + part[tid + 64]) * inv;
}

// ---------------- launch ----------------
extern "C" void kernel_launch(void* const* d_in, const int* in_sizes, int n_in,
                              void* d_out, int out_size)
{
    const float* x      = (const float*)d_in[0];
    const float* ln1_g  = (const float*)d_in[1];
    const float* ln1_b  = (const float*)d_in[2];
    const float* ln2_g  = (const float*)d_in[3];
    const float* ln2_b  = (const float*)d_in[4];
    const float* w_qkv  = (const float*)d_in[5];
    const float* b_qkv  = (const float*)d_in[6];
    const float* w_proj = (const float*)d_in[7];
    const float* b_proj = (const float*)d_in[8];
    const float* w_fc1  = (const float*)d_in[9];
    const float* b_fc1  = (const float*)d_in[10];
    const float* w_fc2  = (const float*)d_in[11];
    const float* b_fc2  = (const float*)d_in[12];
    float* out = (float*)d_out;

    void *p_h, *p_qkv, *p_o, *p_x1, *p_act;
    cudaGetSymbolAddress(&p_h,   g_h);
    cudaGetSymbolAddress(&p_qkv, g_qkv);
    cudaGetSymbolAddress(&p_o,   g_o);
    cudaGetSymbolAddress(&p_x1,  g_x1);
    cudaGetSymbolAddress(&p_act, g_act);
    float* h   = (float*)p_h;
    float* qkv = (float*)p_qkv;
    float* o   = (float*)p_o;
    float* x1  = (float*)p_x1;
    float* act = (float*)p_act;

    // 1. LN1
    ln_kernel<<<TOK, 256>>>(x, h, ln1_g, ln1_b);
    // 2. QKV = h @ w_qkv + b_qkv          [4096 x 3072]
    gemm_kernel<false, false><<<dim3(3 * EMB / 128, TOK / 128), 256>>>(
        h, w_qkv, b_qkv, nullptr, qkv, TOK, 3 * EMB, EMB);
    // 3. attention -> o                    [4096 x 1024]
    attn_kernel<<<dim3(2 * NH, SEQ), 128>>>(qkv, o);
    // 4. x1 = x + o @ w_proj + b_proj
    gemm_kernel<false, true><<<dim3(EMB / 128, TOK / 128), 256>>>(
        o, w_proj, b_proj, x, x1, TOK, EMB, EMB);
    // 5. LN2
    ln_kernel<<<TOK, 256>>>(x1, h, ln2_g, ln2_b);
    // 6. act = gelu(h @ w_fc1 + b_fc1)     [4096 x 4096]
    gemm_kernel<true, false><<<dim3(MLP / 128, TOK / 128), 256>>>(
        h, w_fc1, b_fc1, nullptr, act, TOK, MLP, EMB);
    // 7. out = x1 + act @ w_fc2 + b_fc2
    gemm_kernel<false, true><<<dim3(EMB / 128, TOK / 128), 256>>>(
        act, w_fc2, b_fc2, x1, out, TOK, EMB, MLP);
}

// round 3
// speedup vs baseline: 3.5563x; 3.5563x over previous
#include <cuda_runtime.h>
#include <cuda_fp16.h>
#include <math.h>
#include <stdint.h>

// ---------------- problem constants ----------------
#define TOK   4096
#define EMB   1024
#define NH    16
#define HD    64
#define SEQ   2048
#define MLP   4096
#define LN_EPS 1e-5f

// ---------------- scratch ----------------
static __device__ float g_h  [(size_t)TOK * EMB];
static __device__ float g_qkv[(size_t)TOK * 3 * EMB];
static __device__ float g_o  [(size_t)TOK * EMB];
static __device__ float g_x1 [(size_t)TOK * EMB];
static __device__ float g_act[(size_t)TOK * MLP];

// ---------------- helpers ----------------
__device__ __forceinline__ uint32_t smem_u32(const void* p) {
    uint32_t a;
    asm("{ .reg .u64 t; cvta.to.shared.u64 t, %1; cvt.u32.u64 %0, t; }" : "=r"(a) : "l"(p));
    return a;
}
__device__ __forceinline__ void sts64(uint32_t addr, uint32_t a, uint32_t b) {
    asm volatile("st.shared.v2.b32 [%0], {%1, %2};" :: "r"(addr), "r"(a), "r"(b));
}
__device__ __forceinline__ uint32_t h2u(__half2 h) { return *(uint32_t*)&h; }
// swizzle for 64-byte rows: chunk(16B) bits [4:6) ^= (row>>1)&3  (row = off>>6)
__device__ __forceinline__ uint32_t swz(uint32_t off) {
    return off ^ (((off >> 7) & 3u) << 4);
}
__device__ __forceinline__ void ldsm_x4(uint32_t addr, uint32_t* r) {
    asm volatile("ldmatrix.sync.aligned.m8n8.x4.shared.b16 {%0,%1,%2,%3}, [%4];"
        : "=r"(r[0]), "=r"(r[1]), "=r"(r[2]), "=r"(r[3]) : "r"(addr));
}
__device__ __forceinline__ void mma16816(float* d, const uint32_t* a, const uint32_t* b) {
    asm volatile("mma.sync.aligned.m16n8k16.row.col.f32.f16.f16.f32 "
        "{%0,%1,%2,%3}, {%4,%5,%6,%7}, {%8,%9}, {%0,%1,%2,%3};"
        : "+f"(d[0]), "+f"(d[1]), "+f"(d[2]), "+f"(d[3])
        : "r"(a[0]), "r"(a[1]), "r"(a[2]), "r"(a[3]), "r"(b[0]), "r"(b[1]));
}
__device__ __forceinline__ float gelu_exact(float x) {
    return 0.5f * x * (1.f + erff(x * 0.70710678118654752f));
}

// =====================================================================
// HMMA GEMM: fp16 hi/lo split (3 mma terms), tile 128x128, BK=32,
// 8 warps (2M x 4N), double-buffered smem.
// MODE: 0 = bias, 1 = bias+gelu, 2 = bias+res
// =====================================================================
#define GEMM_SMEM (2 * 32768)

template<int MODE>
__global__ void __launch_bounds__(256, 2)
mma_gemm(const float* __restrict__ A, const float* __restrict__ B,
         const float* __restrict__ bias, const float* __restrict__ res,
         float* __restrict__ C, int M, int N, int K)
{
    extern __shared__ char dsm[];
    const uint32_t base = smem_u32(dsm);

    const int tid  = threadIdx.x;
    const int lane = tid & 31, wid = tid >> 5;
    const int wm = (wid & 1) * 64;
    const int wn = (wid >> 1) * 32;
    const int bm = blockIdx.y * 128, bn = blockIdx.x * 128;

    const int am  = tid >> 1;
    const int ak  = (tid & 1) * 16;
    const int bk  = (tid & 7) * 4;
    const int bnq = (tid >> 3) * 4;

    const float* Ap = A + (size_t)(bm + am) * K + ak;
    const float* Bp = B + (size_t)bk * N + bn + bnq;

    float acc[4][4][4];
#pragma unroll
    for (int i = 0; i < 4; ++i)
#pragma unroll
        for (int j = 0; j < 4; ++j)
#pragma unroll
            for (int c = 0; c < 4; ++c) acc[i][j][c] = 0.f;

    const int nch = K / 32;
    float4 bufA[4], bufB[4];

    auto ldgA = [&](int kc) {
#pragma unroll
        for (int j = 0; j < 4; ++j)
            bufA[j] = *(const float4*)(Ap + kc * 32 + j * 4);
    };
    auto ldgB = [&](int kc) {
#pragma unroll
        for (int j = 0; j < 4; ++j)
            bufB[j] = *(const float4*)(Bp + (size_t)(kc * 32 + j) * N);
    };
    auto stsA = [&](int buf) {
        const uint32_t sAhi = base + buf * 32768u;
        const uint32_t sAlo = sAhi + 8192u;
#pragma unroll
        for (int j = 0; j < 4; ++j) {
            float4 v = bufA[j];
            __half2 h0 = __floats2half2_rn(v.x, v.y);
            __half2 h1 = __floats2half2_rn(v.z, v.w);
            float2 f0 = __half22float2(h0);
            float2 f1 = __half22float2(h1);
            __half2 l0 = __floats2half2_rn(v.x - f0.x, v.y - f0.y);
            __half2 l1 = __floats2half2_rn(v.z - f1.x, v.w - f1.y);
            uint32_t off = swz((uint32_t)(am * 64 + (ak + j * 4) * 2));
            sts64(sAhi + off, h2u(h0), h2u(h1));
            sts64(sAlo + off, h2u(l0), h2u(l1));
        }
    };
    auto stsB = [&](int buf) {
        const uint32_t sBhi = base + buf * 32768u + 16384u;
        const uint32_t sBlo = sBhi + 8192u;
        float vk[4][4];
#pragma unroll
        for (int j = 0; j < 4; ++j) {
            vk[j][0] = bufB[j].x; vk[j][1] = bufB[j].y;
            vk[j][2] = bufB[j].z; vk[j][3] = bufB[j].w;
        }
#pragma unroll
        for (int i = 0; i < 4; ++i) {
            __half2 h01 = __floats2half2_rn(vk[0][i], vk[1][i]);
            __half2 h23 = __floats2half2_rn(vk[2][i], vk[3][i]);
            float2 f01 = __half22float2(h01);
            float2 f23 = __half22float2(h23);
            __half2 l01 = __floats2half2_rn(vk[0][i] - f01.x, vk[1][i] - f01.y);
            __half2 l23 = __floats2half2_rn(vk[2][i] - f23.x, vk[3][i] - f23.y);
            uint32_t off = swz((uint32_t)((bnq + i) * 64 + bk * 2));
            sts64(sBhi + off, h2u(h01), h2u(h23));
            sts64(sBlo + off, h2u(l01), h2u(l23));
        }
    };

    auto ldA = [&](uint32_t sa, int ks, uint32_t AF[4][4]) {
        const int g = lane >> 3;
        const int r = wm + (g & 1) * 8 + (lane & 7);
        const int cb = ks * 32 + (g >> 1) * 16;
#pragma unroll
        for (int mt = 0; mt < 4; ++mt)
            ldsm_x4(sa + swz((uint32_t)((r + mt * 16) * 64 + cb)), AF[mt]);
    };
    auto ldB = [&](uint32_t sb, int ks, uint32_t BF[4][2]) {
        const int g = lane >> 3;
        const int r = wn + (g >> 1) * 8 + (lane & 7);
        const int cb = ks * 32 + (g & 1) * 16;
        uint32_t t[4];
        ldsm_x4(sb + swz((uint32_t)(r * 64 + cb)), t);
        BF[0][0] = t[0]; BF[0][1] = t[1]; BF[1][0] = t[2]; BF[1][1] = t[3];
        ldsm_x4(sb + swz((uint32_t)((r + 16) * 64 + cb)), t);
        BF[2][0] = t[0]; BF[2][1] = t[1]; BF[3][0] = t[2]; BF[3][1] = t[3];
    };
    auto mmaAll = [&](uint32_t AF[4][4], uint32_t BF[4][2]) {
#pragma unroll
        for (int mt = 0; mt < 4; ++mt)
#pragma unroll
            for (int nt = 0; nt < 4; ++nt)
                mma16816(acc[mt][nt], AF[mt], BF[nt]);
    };
    auto compute = [&](int buf) {
        const uint32_t sAhi = base + buf * 32768u;
        const uint32_t sAlo = sAhi + 8192u;
        const uint32_t sBhi = sAhi + 16384u;
        const uint32_t sBlo = sAhi + 24576u;
#pragma unroll
        for (int ks = 0; ks < 2; ++ks) {
            uint32_t AF[4][4], BF[4][2];
            ldA(sAhi, ks, AF);
            ldB(sBhi, ks, BF);
            mmaAll(AF, BF);
            ldA(sAlo, ks, AF);
            mmaAll(AF, BF);
            ldA(sAhi, ks, AF);
            ldB(sBlo, ks, BF);
            mmaAll(AF, BF);
        }
    };

    ldgA(0); stsA(0);
    ldgB(0); stsB(0);
    __syncthreads();

    for (int kc = 0; kc < nch; ++kc) {
        const int cur = kc & 1;
        const bool more = (kc + 1 < nch);
        if (more) ldgA(kc + 1);
        compute(cur);
        if (more) {
            stsA(cur ^ 1);
            ldgB(kc + 1);
            stsB(cur ^ 1);
        }
        __syncthreads();
    }

#pragma unroll
    for (int mt = 0; mt < 4; ++mt) {
#pragma unroll
        for (int nt = 0; nt < 4; ++nt) {
            const int col = bn + wn + nt * 8 + (lane & 3) * 2;
            const float b0 = bias[col], b1 = bias[col + 1];
#pragma unroll
            for (int dp = 0; dp < 2; ++dp) {
                const int row = bm + wm + mt * 16 + (lane >> 2) + dp * 8;
                float o0 = acc[mt][nt][dp * 2 + 0] + b0;
                float o1 = acc[mt][nt][dp * 2 + 1] + b1;
                if (MODE == 1) { o0 = gelu_exact(o0); o1 = gelu_exact(o1); }
                if (MODE == 2) {
                    const float2 rv = *(const float2*)(res + (size_t)row * N + col);
                    o0 += rv.x; o1 += rv.y;
                }
                float2 ov; ov.x = o0; ov.y = o1;
                *(float2*)(C + (size_t)row * N + col) = ov;
            }
        }
    }
}

// =====================================================================
// Flash-style attention (fp32 FFMA). One CTA = (b,h) x 128 queries.
// =====================================================================
#define ATT_SMEM ((64*132 + 64*132 + 128*68 + 128*132 + 128*17 + 3*128) * 4)

__global__ void __launch_bounds__(256, 1)
attn_kernel(const float* __restrict__ qkv, float* __restrict__ o)
{
    extern __shared__ float sm[];
    float* QT  = sm;
    float* KT  = QT + 64 * 132;
    float* VS  = KT + 64 * 132;
    float* PS  = VS + 128 * 68;
    float* RED = PS + 128 * 132;
    float* MS  = RED + 128 * 17;
    float* LS  = MS + 128;
    float* FS  = LS + 128;

    const int tid = threadIdx.x;
    const int tx = tid & 15, ty = tid >> 4;
    const int b = blockIdx.x >> 4, h = blockIdx.x & 15;
    const int q0g = blockIdx.y * 128;
    const size_t tb = (size_t)b * SEQ;
    const size_t RS = 3 * EMB;

    {
        const int r = tid >> 1;
        const int d0 = (tid & 1) * 32;
        const float* qp = qkv + (tb + q0g + r) * RS + h * HD + d0;
#pragma unroll
        for (int j = 0; j < 8; ++j) {
            float4 v = *(const float4*)(qp + j * 4);
            int d = d0 + j * 4;
            QT[(d + 0) * 132 + r] = v.x * 0.125f;
            QT[(d + 1) * 132 + r] = v.y * 0.125f;
            QT[(d + 2) * 132 + r] = v.z * 0.125f;
            QT[(d + 3) * 132 + r] = v.w * 0.125f;
        }
    }
    if (tid < 128) { MS[tid] = -INFINITY; LS[tid] = 0.f; }

    float oacc[8][4];
#pragma unroll
    for (int i = 0; i < 8; ++i)
#pragma unroll
        for (int c = 0; c < 4; ++c) oacc[i][c] = 0.f;

    for (int kt = 0; kt < SEQ / 128; ++kt) {
        __syncthreads();
        {
            const int r = tid >> 1;
            const int d0 = (tid & 1) * 32;
            const float* kp = qkv + (tb + kt * 128 + r) * RS + EMB + h * HD + d0;
            const float* vp = kp + EMB;
#pragma unroll
            for (int j = 0; j < 8; ++j) {
                float4 kv = *(const float4*)(kp + j * 4);
                int d = d0 + j * 4;
                KT[(d + 0) * 132 + r] = kv.x;
                KT[(d + 1) * 132 + r] = kv.y;
                KT[(d + 2) * 132 + r] = kv.z;
                KT[(d + 3) * 132 + r] = kv.w;
                float4 vv = *(const float4*)(vp + j * 4);
                *(float4*)&VS[r * 68 + d] = vv;
            }
        }
        __syncthreads();

        float s[8][8];
#pragma unroll
        for (int i = 0; i < 8; ++i)
#pragma unroll
            for (int j = 0; j < 8; ++j) s[i][j] = 0.f;
        for (int kk = 0; kk < 64; ++kk) {
            float a[8], bb[8];
            *(float4*)(a)      = *(const float4*)&QT[kk * 132 + ty * 8];
            *(float4*)(a + 4)  = *(const float4*)&QT[kk * 132 + ty * 8 + 4];
            *(float4*)(bb)     = *(const float4*)&KT[kk * 132 + tx * 8];
            *(float4*)(bb + 4) = *(const float4*)&KT[kk * 132 + tx * 8 + 4];
#pragma unroll
            for (int i = 0; i < 8; ++i)
#pragma unroll
                for (int j = 0; j < 8; ++j)
                    s[i][j] = fmaf(a[i], bb[j], s[i][j]);
        }
#pragma unroll
        for (int i = 0; i < 8; ++i) {
            float pm = s[i][0];
#pragma unroll
            for (int j = 1; j < 8; ++j) pm = fmaxf(pm, s[i][j]);
            RED[(ty * 8 + i) * 17 + tx] = pm;
        }
        __syncthreads();
        if (tid < 128) {
            float m = MS[tid], mn = m;
#pragma unroll
            for (int t = 0; t < 16; ++t) mn = fmaxf(mn, RED[tid * 17 + t]);
            float f = __expf(m - mn);
            MS[tid] = mn; FS[tid] = f; LS[tid] *= f;
        }
        __syncthreads();
#pragma unroll
        for (int i = 0; i < 8; ++i) {
            const float mrow = MS[ty * 8 + i];
            float rs = 0.f;
#pragma unroll
            for (int j = 0; j < 8; ++j) {
                float p = __expf(s[i][j] - mrow);
                rs += p;
                PS[(tx * 8 + j) * 132 + (ty * 8 + i)] = p;
            }
            RED[(ty * 8 + i) * 17 + tx] = rs;
        }
        __syncthreads();
        if (tid < 128) {
            float acc2 = 0.f;
#pragma unroll
            for (int t = 0; t < 16; ++t) acc2 += RED[tid * 17 + t];
            LS[tid] += acc2;
        }
        float fac[8];
#pragma unroll
        for (int i = 0; i < 8; ++i) fac[i] = FS[ty * 8 + i];
#pragma unroll
        for (int i = 0; i < 8; ++i)
#pragma unroll
            for (int c = 0; c < 4; ++c) oacc[i][c] *= fac[i];
#pragma unroll 2
        for (int j = 0; j < 128; ++j) {
            float a[8];
            *(float4*)(a)     = *(const float4*)&PS[j * 132 + ty * 8];
            *(float4*)(a + 4) = *(const float4*)&PS[j * 132 + ty * 8 + 4];
            float4 vv = *(const float4*)&VS[j * 68 + tx * 4];
#pragma unroll
            for (int i = 0; i < 8; ++i) {
                oacc[i][0] = fmaf(a[i], vv.x, oacc[i][0]);
                oacc[i][1] = fmaf(a[i], vv.y, oacc[i][1]);
                oacc[i][2] = fmaf(a[i], vv.z, oacc[i][2]);
                oacc[i][3] = fmaf(a[i], vv.w, oacc[i][3]);
            }
        }
    }
    __syncthreads();
#pragma unroll
    for (int i = 0; i < 8; ++i) {
        float linv = 1.f / LS[ty * 8 + i];
        float4 ov;
        ov.x = oacc[i][0] * linv; ov.y = oacc[i][1] * linv;
        ov.z = oacc[i][2] * linv; ov.w = oacc[i][3] * linv;
        *(float4*)(o + (tb + q0g + ty * 8 + i) * EMB + h * HD + tx * 4) = ov;
    }
}

// ---------------- LayerNorm ----------------
__global__ void ln_kernel(const float* __restrict__ in, float* __restrict__ out,
                          const float* __restrict__ gam, const float* __restrict__ bet)
{
    __shared__ float red[32], red2[32];
    __shared__ float s_mu, s_rstd;
    const int row = blockIdx.x;
    const float* x = in + (size_t)row * EMB;
    float* y = out + (size_t)row * EMB;
    const int tid = threadIdx.x;

    float v[4];
    float s = 0.f, sq = 0.f;
#pragma unroll
    for (int i = 0; i < 4; ++i) {
        v[i] = x[tid + i * 256];
        s += v[i]; sq += v[i] * v[i];
    }
    const unsigned FULL = 0xffffffffu;
#pragma unroll
    for (int o = 16; o > 0; o >>= 1) {
        s  += __shfl_down_sync(FULL, s, o);
        sq += __shfl_down_sync(FULL, sq, o);
    }
    int warp = tid >> 5, lane = tid & 31;
    if (lane == 0) { red[warp] = s; red2[warp] = sq; }
    __syncthreads();
    if (warp == 0) {
        s  = (lane < 8) ? red[lane]  : 0.f;
        sq = (lane < 8) ? red2[lane] : 0.f;
#pragma unroll
        for (int o = 4; o > 0; o >>= 1) {
            s  += __shfl_down_sync(FULL, s, o);
            sq += __shfl_down_sync(FULL, sq, o);
        }
        if (lane == 0) {
            float mu = s * (1.f / EMB);
            float var = sq * (1.f / EMB) - mu * mu;
            s_mu = mu; s_rstd = rsqrtf(var + LN_EPS);
        }
    }
    __syncthreads();
    float mu = s_mu, rstd = s_rstd;
#pragma unroll
    for (int i = 0; i < 4; ++i) {
        int c = tid + i * 256;
        y[c] = (v[i] - mu) * rstd * gam[c] + bet[c];
    }
}

// ---------------- launch ----------------
extern "C" void kernel_launch(void* const* d_in, const int* in_sizes, int n_in,
                              void* d_out, int out_size)
{
    const float* x      = (const float*)d_in[0];
    const float* ln1_g  = (const float*)d_in[1];
    const float* ln1_b  = (const float*)d_in[2];
    const float* ln2_g  = (const float*)d_in[3];
    const float* ln2_b  = (const float*)d_in[4];
    const float* w_qkv  = (const float*)d_in[5];
    const float* b_qkv  = (const float*)d_in[6];
    const float* w_proj = (const float*)d_in[7];
    const float* b_proj = (const float*)d_in[8];
    const float* w_fc1  = (const float*)d_in[9];
    const float* b_fc1  = (const float*)d_in[10];
    const float* w_fc2  = (const float*)d_in[11];
    const float* b_fc2  = (const float*)d_in[12];
    float* out = (float*)d_out;

    void *p_h, *p_qkv, *p_o, *p_x1, *p_act;
    cudaGetSymbolAddress(&p_h, g_h);
    cudaGetSymbolAddress(&p_qkv, g_qkv);
    cudaGetSymbolAddress(&p_o, g_o);
    cudaGetSymbolAddress(&p_x1, g_x1);
    cudaGetSymbolAddress(&p_act, g_act);
    float* h   = (float*)p_h;
    float* qkv = (float*)p_qkv;
    float* o   = (float*)p_o;
    float* x1  = (float*)p_x1;
    float* act = (float*)p_act;

    cudaFuncSetAttribute(mma_gemm<0>, cudaFuncAttributeMaxDynamicSharedMemorySize, GEMM_SMEM);
    cudaFuncSetAttribute(mma_gemm<1>, cudaFuncAttributeMaxDynamicSharedMemorySize, GEMM_SMEM);
    cudaFuncSetAttribute(mma_gemm<2>, cudaFuncAttributeMaxDynamicSharedMemorySize, GEMM_SMEM);
    cudaFuncSetAttribute(attn_kernel, cudaFuncAttributeMaxDynamicSharedMemorySize, ATT_SMEM);

    ln_kernel<<<TOK, 256>>>(x, h, ln1_g, ln1_b);
    mma_gemm<0><<<dim3(3 * EMB / 128, TOK / 128), 256, GEMM_SMEM>>>(
        h, w_qkv, b_qkv, nullptr, qkv, TOK, 3 * EMB, EMB);
    attn_kernel<<<dim3(2 * NH, SEQ / 128), 256, ATT_SMEM>>>(qkv, o);
    mma_gemm<2><<<dim3(EMB / 128, TOK / 128), 256, GEMM_SMEM>>>(
        o, w_proj, b_proj, x, x1, TOK, EMB, EMB);
    ln_kernel<<<TOK, 256>>>(x1, h, ln2_g, ln2_b);
    mma_gemm<1><<<dim3(MLP / 128, TOK / 128), 256, GEMM_SMEM>>>(
        h, w_fc1, b_fc1, nullptr, act, TOK, MLP, EMB);
    mma_gemm<2><<<dim3(EMB / 128, TOK / 128), 256, GEMM_SMEM>>>(
        act, w_fc2, b_fc2, x1, out, TOK, EMB, MLP);
}

// round 4
// speedup vs baseline: 7.8636x; 2.2111x over previous
#include <cuda_runtime.h>
#include <cuda_fp16.h>
#include <math.h>
#include <stdint.h>

// ---------------- problem constants ----------------
#define TOK   4096
#define EMB   1024
#define NH    16
#define HD    64
#define SEQ   2048
#define MLP   4096
#define LN_EPS 1e-5f

// ---------------- scratch ----------------
static __device__ float g_h  [(size_t)TOK * EMB];
static __device__ float g_qkv[(size_t)TOK * 3 * EMB];
static __device__ float g_o  [(size_t)TOK * EMB];
static __device__ float g_x1 [(size_t)TOK * EMB];
static __device__ float g_act[(size_t)TOK * MLP];

// ---------------- helpers ----------------
__device__ __forceinline__ uint32_t smem_u32(const void* p) {
    uint32_t a;
    asm("{ .reg .u64 t; cvta.to.shared.u64 t, %1; cvt.u32.u64 %0, t; }" : "=r"(a) : "l"(p));
    return a;
}
__device__ __forceinline__ void sts64(uint32_t addr, uint32_t a, uint32_t b) {
    asm volatile("st.shared.v2.b32 [%0], {%1, %2};" :: "r"(addr), "r"(a), "r"(b));
}
__device__ __forceinline__ uint32_t h2u(__half2 h) { return *(uint32_t*)&h; }
// swizzle for 64-byte rows (GEMM): 16B chunk bits [4:6) ^= (row>>1)&3
__device__ __forceinline__ uint32_t swz(uint32_t off) {
    return off ^ (((off >> 7) & 3u) << 4);
}
// swizzle for 128-byte rows (attention): 16B chunk bits [4:7) ^= row&7
__device__ __forceinline__ uint32_t sw128(uint32_t off) {
    return off ^ ((off >> 3) & 0x70u);
}
__device__ __forceinline__ void ldsm_x4(uint32_t addr, uint32_t* r) {
    asm volatile("ldmatrix.sync.aligned.m8n8.x4.shared.b16 {%0,%1,%2,%3}, [%4];"
        : "=r"(r[0]), "=r"(r[1]), "=r"(r[2]), "=r"(r[3]) : "r"(addr));
}
__device__ __forceinline__ void ldsm_x4_t(uint32_t addr, uint32_t* r) {
    asm volatile("ldmatrix.sync.aligned.m8n8.x4.trans.shared.b16 {%0,%1,%2,%3}, [%4];"
        : "=r"(r[0]), "=r"(r[1]), "=r"(r[2]), "=r"(r[3]) : "r"(addr));
}
__device__ __forceinline__ void mma16816(float* d, const uint32_t* a, const uint32_t* b) {
    asm volatile("mma.sync.aligned.m16n8k16.row.col.f32.f16.f16.f32 "
        "{%0,%1,%2,%3}, {%4,%5,%6,%7}, {%8,%9}, {%0,%1,%2,%3};"
        : "+f"(d[0]), "+f"(d[1]), "+f"(d[2]), "+f"(d[3])
        : "r"(a[0]), "r"(a[1]), "r"(a[2]), "r"(a[3]), "r"(b[0]), "r"(b[1]));
}
__device__ __forceinline__ float gelu_exact(float x) {
    return 0.5f * x * (1.f + erff(x * 0.70710678118654752f));
}

// =====================================================================
// HMMA GEMM: fp16 hi/lo split (3 mma terms), tile 128x128, BK=32,
// 8 warps (2M x 4N), double-buffered smem.
// Term order (Alo*Bhi),(Ahi*Bhi),(Ahi*Blo) -> 12 ldsm/ks instead of 16.
// MODE: 0 = bias, 1 = bias+gelu, 2 = bias+res
// =====================================================================
#define GEMM_SMEM (2 * 32768)

template<int MODE>
__global__ void __launch_bounds__(256, 2)
mma_gemm(const float* __restrict__ A, const float* __restrict__ B,
         const float* __restrict__ bias, const float* __restrict__ res,
         float* __restrict__ C, int M, int N, int K)
{
    extern __shared__ char dsm[];
    const uint32_t base = smem_u32(dsm);

    const int tid  = threadIdx.x;
    const int lane = tid & 31, wid = tid >> 5;
    const int wm = (wid & 1) * 64;
    const int wn = (wid >> 1) * 32;
    const int bm = blockIdx.y * 128, bn = blockIdx.x * 128;

    const int am  = tid >> 1;
    const int ak  = (tid & 1) * 16;
    const int bk  = (tid & 7) * 4;
    const int bnq = (tid >> 3) * 4;

    const float* Ap = A + (size_t)(bm + am) * K + ak;
    const float* Bp = B + (size_t)bk * N + bn + bnq;

    float acc[4][4][4];
#pragma unroll
    for (int i = 0; i < 4; ++i)
#pragma unroll
        for (int j = 0; j < 4; ++j)
#pragma unroll
            for (int c = 0; c < 4; ++c) acc[i][j][c] = 0.f;

    const int nch = K / 32;
    float4 bufA[4], bufB[4];

    auto ldgA = [&](int kc) {
#pragma unroll
        for (int j = 0; j < 4; ++j)
            bufA[j] = *(const float4*)(Ap + kc * 32 + j * 4);
    };
    auto ldgB = [&](int kc) {
#pragma unroll
        for (int j = 0; j < 4; ++j)
            bufB[j] = *(const float4*)(Bp + (size_t)(kc * 32 + j) * N);
    };
    auto stsA = [&](int buf) {
        const uint32_t sAhi = base + buf * 32768u;
        const uint32_t sAlo = sAhi + 8192u;
#pragma unroll
        for (int j = 0; j < 4; ++j) {
            float4 v = bufA[j];
            __half2 h0 = __floats2half2_rn(v.x, v.y);
            __half2 h1 = __floats2half2_rn(v.z, v.w);
            float2 f0 = __half22float2(h0);
            float2 f1 = __half22float2(h1);
            __half2 l0 = __floats2half2_rn(v.x - f0.x, v.y - f0.y);
            __half2 l1 = __floats2half2_rn(v.z - f1.x, v.w - f1.y);
            uint32_t off = swz((uint32_t)(am * 64 + (ak + j * 4) * 2));
            sts64(sAhi + off, h2u(h0), h2u(h1));
            sts64(sAlo + off, h2u(l0), h2u(l1));
        }
    };
    auto stsB = [&](int buf) {
        const uint32_t sBhi = base + buf * 32768u + 16384u;
        const uint32_t sBlo = sBhi + 8192u;
        float vk[4][4];
#pragma unroll
        for (int j = 0; j < 4; ++j) {
            vk[j][0] = bufB[j].x; vk[j][1] = bufB[j].y;
            vk[j][2] = bufB[j].z; vk[j][3] = bufB[j].w;
        }
#pragma unroll
        for (int i = 0; i < 4; ++i) {
            __half2 h01 = __floats2half2_rn(vk[0][i], vk[1][i]);
            __half2 h23 = __floats2half2_rn(vk[2][i], vk[3][i]);
            float2 f01 = __half22float2(h01);
            float2 f23 = __half22float2(h23);
            __half2 l01 = __floats2half2_rn(vk[0][i] - f01.x, vk[1][i] - f01.y);
            __half2 l23 = __floats2half2_rn(vk[2][i] - f23.x, vk[3][i] - f23.y);
            uint32_t off = swz((uint32_t)((bnq + i) * 64 + bk * 2));
            sts64(sBhi + off, h2u(h01), h2u(h23));
            sts64(sBlo + off, h2u(l01), h2u(l23));
        }
    };

    auto ldA = [&](uint32_t sa, int ks, uint32_t AF[4][4]) {
        const int g = lane >> 3;
        const int r = wm + (g & 1) * 8 + (lane & 7);
        const int cb = ks * 32 + (g >> 1) * 16;
#pragma unroll
        for (int mt = 0; mt < 4; ++mt)
            ldsm_x4(sa + swz((uint32_t)((r + mt * 16) * 64 + cb)), AF[mt]);
    };
    auto ldB = [&](uint32_t sb, int ks, uint32_t BF[4][2]) {
        const int g = lane >> 3;
        const int r = wn + (g >> 1) * 8 + (lane & 7);
        const int cb = ks * 32 + (g & 1) * 16;
        uint32_t t[4];
        ldsm_x4(sb + swz((uint32_t)(r * 64 + cb)), t);
        BF[0][0] = t[0]; BF[0][1] = t[1]; BF[1][0] = t[2]; BF[1][1] = t[3];
        ldsm_x4(sb + swz((uint32_t)((r + 16) * 64 + cb)), t);
        BF[2][0] = t[0]; BF[2][1] = t[1]; BF[3][0] = t[2]; BF[3][1] = t[3];
    };
    auto mmaAll = [&](uint32_t AF[4][4], uint32_t BF[4][2]) {
#pragma unroll
        for (int mt = 0; mt < 4; ++mt)
#pragma unroll
            for (int nt = 0; nt < 4; ++nt)
                mma16816(acc[mt][nt], AF[mt], BF[nt]);
    };
    auto compute = [&](int buf) {
        const uint32_t sAhi = base + buf * 32768u;
        const uint32_t sAlo = sAhi + 8192u;
        const uint32_t sBhi = sAhi + 16384u;
        const uint32_t sBlo = sAhi + 24576u;
#pragma unroll
        for (int ks = 0; ks < 2; ++ks) {
            uint32_t AF[4][4], BF[4][2];
            ldA(sAlo, ks, AF);         // Alo
            ldB(sBhi, ks, BF);         // Bhi
            mmaAll(AF, BF);            // Alo*Bhi
            ldA(sAhi, ks, AF);         // Ahi (stays for both B terms)
            mmaAll(AF, BF);            // Ahi*Bhi
            ldB(sBlo, ks, BF);         // Blo
            mmaAll(AF, BF);            // Ahi*Blo
        }
    };

    ldgA(0); stsA(0);
    ldgB(0); stsB(0);
    __syncthreads();

    for (int kc = 0; kc < nch; ++kc) {
        const int cur = kc & 1;
        const bool more = (kc + 1 < nch);
        if (more) ldgA(kc + 1);
        compute(cur);
        if (more) {
            stsA(cur ^ 1);
            ldgB(kc + 1);
            stsB(cur ^ 1);
        }
        __syncthreads();
    }

#pragma unroll
    for (int mt = 0; mt < 4; ++mt) {
#pragma unroll
        for (int nt = 0; nt < 4; ++nt) {
            const int col = bn + wn + nt * 8 + (lane & 3) * 2;
            const float b0 = bias[col], b1 = bias[col + 1];
#pragma unroll
            for (int dp = 0; dp < 2; ++dp) {
                const int row = bm + wm + mt * 16 + (lane >> 2) + dp * 8;
                float o0 = acc[mt][nt][dp * 2 + 0] + b0;
                float o1 = acc[mt][nt][dp * 2 + 1] + b1;
                if (MODE == 1) { o0 = gelu_exact(o0); o1 = gelu_exact(o1); }
                if (MODE == 2) {
                    const float2 rv = *(const float2*)(res + (size_t)row * N + col);
                    o0 += rv.x; o1 += rv.y;
                }
                float2 ov; ov.x = o0; ov.y = o1;
                *(float2*)(C + (size_t)row * N + col) = ov;
            }
        }
    }
}

// =====================================================================
// HMMA flash attention. CTA = (b, head) x 128 queries, 256 threads.
// 8 warps: mg = wid>>1 (32 q-rows each), kh = wid&1 (64-key half).
// fp16 Q/K/V (no split), fp32 softmax + accumulators.
// smem: Q fp16 [128][64] | region R: K fp16 | V fp16, reused as Obuf fp32.
// =====================================================================
#define ATT_SMEM (16384 + 34816 + 256)

__global__ void __launch_bounds__(256, 1)
attn_mma(const float* __restrict__ qkv, float* __restrict__ o)
{
    extern __shared__ char dynsm[];
    __shared__ float smax[2][128];
    __shared__ float lsum2[2][128];

    const uint32_t Qb = smem_u32(dynsm);
    const uint32_t Kb = Qb + 16384u;
    const uint32_t Vb = Kb + 16384u;
    float* Obuf = (float*)(dynsm + 16384);     // [128][68] fp32, aliases K|V

    const int tid  = threadIdx.x;
    const int lane = tid & 31, wid = tid >> 5;
    const int mg = wid >> 1, kh = wid & 1;
    const int b = blockIdx.x >> 4, hh = blockIdx.x & 15;
    const int q0 = blockIdx.y * 128;
    const size_t tb = (size_t)b * SEQ;
    const size_t RS = 3 * EMB;
    const unsigned FULL = 0xffffffffu;

    // ---- load Q tile (pre-scaled) to smem fp16 ----
    {
        const int r = tid >> 1, c0 = (tid & 1) * 32;
        const float* qp = qkv + (tb + q0 + r) * RS + hh * HD + c0;
#pragma unroll
        for (int j = 0; j < 8; ++j) {
            float4 v = *(const float4*)(qp + j * 4);
            __half2 h0 = __floats2half2_rn(v.x * 0.125f, v.y * 0.125f);
            __half2 h1 = __floats2half2_rn(v.z * 0.125f, v.w * 0.125f);
            sts64(Qb + sw128((uint32_t)(r * 128 + (c0 + j * 4) * 2)), h2u(h0), h2u(h1));
        }
    }
    __syncthreads();

    // ---- preload Q fragments (persistent) ----
    uint32_t QF[2][4][4];
    {
        const int g = lane >> 3;
#pragma unroll
        for (int mt = 0; mt < 2; ++mt)
#pragma unroll
            for (int t = 0; t < 4; ++t) {
                const int r = mg * 32 + mt * 16 + (g & 1) * 8 + (lane & 7);
                const int cb = t * 32 + (g >> 1) * 16;
                ldsm_x4(Qb + sw128((uint32_t)(r * 128 + cb)), QF[mt][t]);
            }
    }

    float Oa[2][8][4];
#pragma unroll
    for (int mt = 0; mt < 2; ++mt)
#pragma unroll
        for (int nt = 0; nt < 8; ++nt)
#pragma unroll
            for (int c = 0; c < 4; ++c) Oa[mt][nt][c] = 0.f;
    float m_run[4], l_run[4];
#pragma unroll
    for (int ri = 0; ri < 4; ++ri) { m_run[ri] = -INFINITY; l_run[ri] = 0.f; }

    for (int kt = 0; kt < SEQ / 128; ++kt) {
        __syncthreads();
        // ---- load K,V tiles to smem fp16 ----
        {
            const int r = tid >> 1, c0 = (tid & 1) * 32;
            const float* kp = qkv + (tb + kt * 128 + r) * RS + EMB + hh * HD + c0;
            const float* vp = kp + EMB;
#pragma unroll
            for (int j = 0; j < 8; ++j) {
                float4 kv = *(const float4*)(kp + j * 4);
                float4 vv = *(const float4*)(vp + j * 4);
                uint32_t off = sw128((uint32_t)(r * 128 + (c0 + j * 4) * 2));
                sts64(Kb + off, h2u(__floats2half2_rn(kv.x, kv.y)),
                                h2u(__floats2half2_rn(kv.z, kv.w)));
                sts64(Vb + off, h2u(__floats2half2_rn(vv.x, vv.y)),
                                h2u(__floats2half2_rn(vv.z, vv.w)));
            }
        }
        __syncthreads();

        // ---- S = Q K^T (warp: 32 rows x 64 keys) ----
        float sacc[2][8][4];
#pragma unroll
        for (int mt = 0; mt < 2; ++mt)
#pragma unroll
            for (int nt = 0; nt < 8; ++nt)
#pragma unroll
                for (int c = 0; c < 4; ++c) sacc[mt][nt][c] = 0.f;

        const int g = lane >> 3;
#pragma unroll
        for (int t = 0; t < 4; ++t) {
#pragma unroll
            for (int pr = 0; pr < 4; ++pr) {
                const int r = kh * 64 + pr * 16 + (g >> 1) * 8 + (lane & 7);
                const int cb = t * 32 + (g & 1) * 16;
                uint32_t tt[4];
                ldsm_x4(Kb + sw128((uint32_t)(r * 128 + cb)), tt);
#pragma unroll
                for (int mt = 0; mt < 2; ++mt) {
                    mma16816(sacc[mt][pr * 2 + 0], QF[mt][t], tt);
                    mma16816(sacc[mt][pr * 2 + 1], QF[mt][t], tt + 2);
                }
            }
        }

        // ---- row max (local -> quad -> cross-warp) ----
        float mloc[4];
#pragma unroll
        for (int ri = 0; ri < 4; ++ri) {
            const int mt = ri >> 1, h = ri & 1;
            float mx = sacc[mt][0][h * 2];
#pragma unroll
            for (int nt = 0; nt < 8; ++nt) {
                mx = fmaxf(mx, sacc[mt][nt][h * 2]);
                mx = fmaxf(mx, sacc[mt][nt][h * 2 + 1]);
            }
            mx = fmaxf(mx, __shfl_xor_sync(FULL, mx, 1));
            mx = fmaxf(mx, __shfl_xor_sync(FULL, mx, 2));
            mloc[ri] = mx;
        }
        if ((lane & 3) == 0) {
#pragma unroll
            for (int ri = 0; ri < 4; ++ri) {
                const int row = mg * 32 + (ri >> 1) * 16 + (ri & 1) * 8 + (lane >> 2);
                smax[kh][row] = mloc[ri];
            }
        }
        __syncthreads();

        float fexp[4];
#pragma unroll
        for (int ri = 0; ri < 4; ++ri) {
            const int row = mg * 32 + (ri >> 1) * 16 + (ri & 1) * 8 + (lane >> 2);
            const float mk = fmaxf(smax[0][row], smax[1][row]);
            const float mn = fmaxf(m_run[ri], mk);
            fexp[ri] = __expf(m_run[ri] - mn);
            m_run[ri] = mn;
            l_run[ri] *= fexp[ri];
        }
        // ---- exp + partial row sums ----
#pragma unroll
        for (int mt = 0; mt < 2; ++mt)
#pragma unroll
            for (int nt = 0; nt < 8; ++nt)
#pragma unroll
                for (int c = 0; c < 4; ++c) {
                    const int ri = mt * 2 + (c >> 1);
                    float p = __expf(sacc[mt][nt][c] - m_run[ri]);
                    sacc[mt][nt][c] = p;
                    l_run[ri] += p;
                }
        // ---- rescale O ----
#pragma unroll
        for (int mt = 0; mt < 2; ++mt)
#pragma unroll
            for (int nt = 0; nt < 8; ++nt)
#pragma unroll
                for (int c = 0; c < 4; ++c)
                    Oa[mt][nt][c] *= fexp[mt * 2 + (c >> 1)];

        // ---- O += P V (k over this warp's 64 keys) ----
#pragma unroll
        for (int k2 = 0; k2 < 4; ++k2) {
            uint32_t pa[2][4];
#pragma unroll
            for (int mt = 0; mt < 2; ++mt) {
                pa[mt][0] = h2u(__floats2half2_rn(sacc[mt][2 * k2][0],     sacc[mt][2 * k2][1]));
                pa[mt][1] = h2u(__floats2half2_rn(sacc[mt][2 * k2][2],     sacc[mt][2 * k2][3]));
                pa[mt][2] = h2u(__floats2half2_rn(sacc[mt][2 * k2 + 1][0], sacc[mt][2 * k2 + 1][1]));
                pa[mt][3] = h2u(__floats2half2_rn(sacc[mt][2 * k2 + 1][2], sacc[mt][2 * k2 + 1][3]));
            }
#pragma unroll
            for (int npr = 0; npr < 4; ++npr) {
                const int r = kh * 64 + k2 * 16 + (g & 1) * 8 + (lane & 7);
                const int cb = npr * 32 + (g >> 1) * 16;
                uint32_t tt[4];
                ldsm_x4_t(Vb + sw128((uint32_t)(r * 128 + cb)), tt);
#pragma unroll
                for (int mt = 0; mt < 2; ++mt) {
                    mma16816(Oa[mt][npr * 2 + 0], pa[mt], tt);
                    mma16816(Oa[mt][npr * 2 + 1], pa[mt], tt + 2);
                }
            }
        }
    }

    // ---- finalize l: quad reduce, publish per half ----
#pragma unroll
    for (int ri = 0; ri < 4; ++ri) {
        l_run[ri] += __shfl_xor_sync(FULL, l_run[ri], 1);
        l_run[ri] += __shfl_xor_sync(FULL, l_run[ri], 2);
    }
    if ((lane & 3) == 0) {
#pragma unroll
        for (int ri = 0; ri < 4; ++ri) {
            const int row = mg * 32 + (ri >> 1) * 16 + (ri & 1) * 8 + (lane >> 2);
            lsum2[kh][row] = l_run[ri];
        }
    }
    __syncthreads();   // V smem reads done; Obuf may now alias K|V

    if (kh == 0) {
#pragma unroll
        for (int mt = 0; mt < 2; ++mt)
#pragma unroll
            for (int nt = 0; nt < 8; ++nt)
#pragma unroll
                for (int h = 0; h < 2; ++h) {
                    const int row = mg * 32 + mt * 16 + h * 8 + (lane >> 2);
                    const int col = nt * 8 + (lane & 3) * 2;
                    float2 v; v.x = Oa[mt][nt][h * 2]; v.y = Oa[mt][nt][h * 2 + 1];
                    *(float2*)&Obuf[row * 68 + col] = v;
                }
    }
    __syncthreads();
    if (kh == 1) {
#pragma unroll
        for (int mt = 0; mt < 2; ++mt)
#pragma unroll
            for (int h = 0; h < 2; ++h) {
                const int row = mg * 32 + mt * 16 + h * 8 + (lane >> 2);
                const float inv = 1.f / (lsum2[0][row] + lsum2[1][row]);
#pragma unroll
                for (int nt = 0; nt < 8; ++nt) {
                    const int col = nt * 8 + (lane & 3) * 2;
                    const float2 pv = *(const float2*)&Obuf[row * 68 + col];
                    float2 ov;
                    ov.x = (Oa[mt][nt][h * 2 + 0] + pv.x) * inv;
                    ov.y = (Oa[mt][nt][h * 2 + 1] + pv.y) * inv;
                    *(float2*)(o + (tb + q0 + row) * EMB + hh * HD + col) = ov;
                }
            }
    }
}

// ---------------- LayerNorm ----------------
__global__ void ln_kernel(const float* __restrict__ in, float* __restrict__ out,
                          const float* __restrict__ gam, const float* __restrict__ bet)
{
    __shared__ float red[32], red2[32];
    __shared__ float s_mu, s_rstd;
    const int row = blockIdx.x;
    const float* x = in + (size_t)row * EMB;
    float* y = out + (size_t)row * EMB;
    const int tid = threadIdx.x;

    float v[4];
    float s = 0.f, sq = 0.f;
#pragma unroll
    for (int i = 0; i < 4; ++i) {
        v[i] = x[tid + i * 256];
        s += v[i]; sq += v[i] * v[i];
    }
    const unsigned FULL = 0xffffffffu;
#pragma unroll
    for (int o = 16; o > 0; o >>= 1) {
        s  += __shfl_down_sync(FULL, s, o);
        sq += __shfl_down_sync(FULL, sq, o);
    }
    int warp = tid >> 5, lane = tid & 31;
    if (lane == 0) { red[warp] = s; red2[warp] = sq; }
    __syncthreads();
    if (warp == 0) {
        s  = (lane < 8) ? red[lane]  : 0.f;
        sq = (lane < 8) ? red2[lane] : 0.f;
#pragma unroll
        for (int o = 4; o > 0; o >>= 1) {
            s  += __shfl_down_sync(FULL, s, o);
            sq += __shfl_down_sync(FULL, sq, o);
        }
        if (lane == 0) {
            float mu = s * (1.f / EMB);
            float var = sq * (1.f / EMB) - mu * mu;
            s_mu = mu; s_rstd = rsqrtf(var + LN_EPS);
        }
    }
    __syncthreads();
    float mu = s_mu, rstd = s_rstd;
#pragma unroll
    for (int i = 0; i < 4; ++i) {
        int c = tid + i * 256;
        y[c] = (v[i] - mu) * rstd * gam[c] + bet[c];
    }
}

// ---------------- launch ----------------
extern "C" void kernel_launch(void* const* d_in, const int* in_sizes, int n_in,
                              void* d_out, int out_size)
{
    const float* x      = (const float*)d_in[0];
    const float* ln1_g  = (const float*)d_in[1];
    const float* ln1_b  = (const float*)d_in[2];
    const float* ln2_g  = (const float*)d_in[3];
    const float* ln2_b  = (const float*)d_in[4];
    const float* w_qkv  = (const float*)d_in[5];
    const float* b_qkv  = (const float*)d_in[6];
    const float* w_proj = (const float*)d_in[7];
    const float* b_proj = (const float*)d_in[8];
    const float* w_fc1  = (const float*)d_in[9];
    const float* b_fc1  = (const float*)d_in[10];
    const float* w_fc2  = (const float*)d_in[11];
    const float* b_fc2  = (const float*)d_in[12];
    float* out = (float*)d_out;

    void *p_h, *p_qkv, *p_o, *p_x1, *p_act;
    cudaGetSymbolAddress(&p_h, g_h);
    cudaGetSymbolAddress(&p_qkv, g_qkv);
    cudaGetSymbolAddress(&p_o, g_o);
    cudaGetSymbolAddress(&p_x1, g_x1);
    cudaGetSymbolAddress(&p_act, g_act);
    float* h   = (float*)p_h;
    float* qkv = (float*)p_qkv;
    float* o   = (float*)p_o;
    float* x1  = (float*)p_x1;
    float* act = (float*)p_act;

    cudaFuncSetAttribute(mma_gemm<0>, cudaFuncAttributeMaxDynamicSharedMemorySize, GEMM_SMEM);
    cudaFuncSetAttribute(mma_gemm<1>, cudaFuncAttributeMaxDynamicSharedMemorySize, GEMM_SMEM);
    cudaFuncSetAttribute(mma_gemm<2>, cudaFuncAttributeMaxDynamicSharedMemorySize, GEMM_SMEM);
    cudaFuncSetAttribute(attn_mma, cudaFuncAttributeMaxDynamicSharedMemorySize, ATT_SMEM);

    ln_kernel<<<TOK, 256>>>(x, h, ln1_g, ln1_b);
    mma_gemm<0><<<dim3(3 * EMB / 128, TOK / 128), 256, GEMM_SMEM>>>(
        h, w_qkv, b_qkv, nullptr, qkv, TOK, 3 * EMB, EMB);
    attn_mma<<<dim3(2 * NH, SEQ / 128), 256, ATT_SMEM>>>(qkv, o);
    mma_gemm<2><<<dim3(EMB / 128, TOK / 128), 256, GEMM_SMEM>>>(
        o, w_proj, b_proj, x, x1, TOK, EMB, EMB);
    ln_kernel<<<TOK, 256>>>(x1, h, ln2_g, ln2_b);
    mma_gemm<1><<<dim3(MLP / 128, TOK / 128), 256, GEMM_SMEM>>>(
        h, w_fc1, b_fc1, nullptr, act, TOK, MLP, EMB);
    mma_gemm<2><<<dim3(EMB / 128, TOK / 128), 256, GEMM_SMEM>>>(
        act, w_fc2, b_fc2, x1, out, TOK, EMB, MLP);
}

// round 5
// speedup vs baseline: 8.0939x; 1.0293x over previous
#include <cuda_runtime.h>
#include <cuda_fp16.h>
#include <math.h>
#include <stdint.h>

// ---------------- problem constants ----------------
#define TOK   4096
#define EMB   1024
#define NH    16
#define HD    64
#define SEQ   2048
#define MLP   4096
#define LN_EPS 1e-5f

// ---------------- scratch ----------------
static __device__ float g_h  [(size_t)TOK * EMB];
static __device__ float g_qkv[(size_t)TOK * 3 * EMB];
static __device__ float g_o  [(size_t)TOK * EMB];
static __device__ float g_x1 [(size_t)TOK * EMB];
static __device__ float g_act[(size_t)TOK * MLP];

// ---------------- helpers ----------------
__device__ __forceinline__ uint32_t smem_u32(const void* p) {
    uint32_t a;
    asm("{ .reg .u64 t; cvta.to.shared.u64 t, %1; cvt.u32.u64 %0, t; }" : "=r"(a) : "l"(p));
    return a;
}
__device__ __forceinline__ void sts64(uint32_t addr, uint32_t a, uint32_t b) {
    asm volatile("st.shared.v2.b32 [%0], {%1, %2};" :: "r"(addr), "r"(a), "r"(b));
}
__device__ __forceinline__ uint32_t h2u(__half2 h) { return *(uint32_t*)&h; }
// swizzle for 64-byte rows (GEMM): 16B chunk bits [4:6) ^= (row>>1)&3
__device__ __forceinline__ uint32_t swz(uint32_t off) {
    return off ^ (((off >> 7) & 3u) << 4);
}
// swizzle for 128-byte rows (attention): 16B chunk bits [4:7) ^= row&7
__device__ __forceinline__ uint32_t sw128(uint32_t off) {
    return off ^ ((off >> 3) & 0x70u);
}
__device__ __forceinline__ void ldsm_x4(uint32_t addr, uint32_t* r) {
    asm volatile("ldmatrix.sync.aligned.m8n8.x4.shared.b16 {%0,%1,%2,%3}, [%4];"
        : "=r"(r[0]), "=r"(r[1]), "=r"(r[2]), "=r"(r[3]) : "r"(addr));
}
__device__ __forceinline__ void ldsm_x4_t(uint32_t addr, uint32_t* r) {
    asm volatile("ldmatrix.sync.aligned.m8n8.x4.trans.shared.b16 {%0,%1,%2,%3}, [%4];"
        : "=r"(r[0]), "=r"(r[1]), "=r"(r[2]), "=r"(r[3]) : "r"(addr));
}
__device__ __forceinline__ void mma16816(float* d, const uint32_t* a, const uint32_t* b) {
    asm volatile("mma.sync.aligned.m16n8k16.row.col.f32.f16.f16.f32 "
        "{%0,%1,%2,%3}, {%4,%5,%6,%7}, {%8,%9}, {%0,%1,%2,%3};"
        : "+f"(d[0]), "+f"(d[1]), "+f"(d[2]), "+f"(d[3])
        : "r"(a[0]), "r"(a[1]), "r"(a[2]), "r"(a[3]), "r"(b[0]), "r"(b[1]));
}
__device__ __forceinline__ float gelu_exact(float x) {
    return 0.5f * x * (1.f + erff(x * 0.70710678118654752f));
}

// =====================================================================
// HMMA GEMM: A fp16 (single), B fp16 hi/lo split (2 mma terms).
// Block tile 256x128, BK=32, 8 warps (4M x 2N) of 64x64 each.
// Double-buffered smem: A 16KB | Bhi 8KB | Blo 8KB  => 32KB/buf, 64KB total.
// MODE: 0 = bias, 1 = bias+gelu, 2 = bias+res
// =====================================================================
#define GEMM_SMEM (2 * 32768)

template<int MODE>
__global__ void __launch_bounds__(256, 1)
mma_gemm(const float* __restrict__ A, const float* __restrict__ B,
         const float* __restrict__ bias, const float* __restrict__ res,
         float* __restrict__ C, int M, int N, int K)
{
    extern __shared__ char dsm[];
    const uint32_t base = smem_u32(dsm);

    const int tid  = threadIdx.x;
    const int lane = tid & 31, wid = tid >> 5;
    const int wm = (wid & 3) * 64;        // warp M offset (4 groups)
    const int wn = (wid >> 2) * 64;       // warp N offset (2 groups)
    const int bm = blockIdx.y * 256, bn = blockIdx.x * 128;

    // global-load mappings
    const int am  = tid;                  // A row 0..255 (32 k floats each)
    const int bk  = (tid & 7) * 4;        // B k start (4 rows)
    const int bnq = (tid >> 3) * 4;       // B n start (4 cols)

    const float* Ap = A + (size_t)(bm + am) * K;
    const float* Bp = B + (size_t)bk * N + bn + bnq;

    float acc[4][8][4];
#pragma unroll
    for (int i = 0; i < 4; ++i)
#pragma unroll
        for (int j = 0; j < 8; ++j)
#pragma unroll
            for (int c = 0; c < 4; ++c) acc[i][j][c] = 0.f;

    const int nch = K / 32;
    float4 bufA[8], bufB[4];

    auto ldgA = [&](int kc) {
#pragma unroll
        for (int j = 0; j < 8; ++j)
            bufA[j] = *(const float4*)(Ap + kc * 32 + j * 4);
    };
    auto ldgB = [&](int kc) {
#pragma unroll
        for (int j = 0; j < 4; ++j)
            bufB[j] = *(const float4*)(Bp + (size_t)(kc * 32 + j) * N);
    };
    auto stsA = [&](int buf) {
        const uint32_t sA = base + buf * 32768u;
#pragma unroll
        for (int j = 0; j < 8; ++j) {
            float4 v = bufA[j];
            __half2 h0 = __floats2half2_rn(v.x, v.y);
            __half2 h1 = __floats2half2_rn(v.z, v.w);
            sts64(sA + swz((uint32_t)(am * 64 + j * 8)), h2u(h0), h2u(h1));
        }
    };
    auto stsB = [&](int buf) {
        const uint32_t sBhi = base + buf * 32768u + 16384u;
        const uint32_t sBlo = sBhi + 8192u;
        float vk[4][4];
#pragma unroll
        for (int j = 0; j < 4; ++j) {
            vk[j][0] = bufB[j].x; vk[j][1] = bufB[j].y;
            vk[j][2] = bufB[j].z; vk[j][3] = bufB[j].w;
        }
#pragma unroll
        for (int i = 0; i < 4; ++i) {
            __half2 h01 = __floats2half2_rn(vk[0][i], vk[1][i]);
            __half2 h23 = __floats2half2_rn(vk[2][i], vk[3][i]);
            float2 f01 = __half22float2(h01);
            float2 f23 = __half22float2(h23);
            __half2 l01 = __floats2half2_rn(vk[0][i] - f01.x, vk[1][i] - f01.y);
            __half2 l23 = __floats2half2_rn(vk[2][i] - f23.x, vk[3][i] - f23.y);
            uint32_t off = swz((uint32_t)((bnq + i) * 64 + bk * 2));
            sts64(sBhi + off, h2u(h01), h2u(h23));
            sts64(sBlo + off, h2u(l01), h2u(l23));
        }
    };

    auto ldA = [&](uint32_t sa, int ks, uint32_t AF[4][4]) {
        const int g = lane >> 3;
        const int r = wm + (g & 1) * 8 + (lane & 7);
        const int cb = ks * 32 + (g >> 1) * 16;
#pragma unroll
        for (int mt = 0; mt < 4; ++mt)
            ldsm_x4(sa + swz((uint32_t)((r + mt * 16) * 64 + cb)), AF[mt]);
    };
    auto ldB = [&](uint32_t sb, int ks, uint32_t BF[8][2]) {
        const int g = lane >> 3;
        const int r = wn + (g >> 1) * 8 + (lane & 7);
        const int cb = ks * 32 + (g & 1) * 16;
#pragma unroll
        for (int p = 0; p < 4; ++p) {
            uint32_t t[4];
            ldsm_x4(sb + swz((uint32_t)((r + p * 16) * 64 + cb)), t);
            BF[2 * p][0] = t[0]; BF[2 * p][1] = t[1];
            BF[2 * p + 1][0] = t[2]; BF[2 * p + 1][1] = t[3];
        }
    };
    auto mmaAll = [&](uint32_t AF[4][4], uint32_t BF[8][2]) {
#pragma unroll
        for (int mt = 0; mt < 4; ++mt)
#pragma unroll
            for (int nt = 0; nt < 8; ++nt)
                mma16816(acc[mt][nt], AF[mt], BF[nt]);
    };
    auto compute = [&](int buf) {
        const uint32_t sA   = base + buf * 32768u;
        const uint32_t sBhi = sA + 16384u;
        const uint32_t sBlo = sA + 24576u;
#pragma unroll
        for (int ks = 0; ks < 2; ++ks) {
            uint32_t AF[4][4], BF[8][2];
            ldA(sA, ks, AF);
            ldB(sBhi, ks, BF);
            mmaAll(AF, BF);          // A * Bhi
            ldB(sBlo, ks, BF);
            mmaAll(AF, BF);          // A * Blo
        }
    };

    ldgA(0); stsA(0);
    ldgB(0); stsB(0);
    __syncthreads();

    for (int kc = 0; kc < nch; ++kc) {
        const int cur = kc & 1;
        const bool more = (kc + 1 < nch);
        if (more) ldgA(kc + 1);
        compute(cur);
        if (more) {
            stsA(cur ^ 1);
            ldgB(kc + 1);
            stsB(cur ^ 1);
        }
        __syncthreads();
    }

    // ---- epilogue ----
#pragma unroll
    for (int mt = 0; mt < 4; ++mt) {
#pragma unroll
        for (int nt = 0; nt < 8; ++nt) {
            const int col = bn + wn + nt * 8 + (lane & 3) * 2;
            const float b0 = bias[col], b1 = bias[col + 1];
#pragma unroll
            for (int dp = 0; dp < 2; ++dp) {
                const int row = bm + wm + mt * 16 + (lane >> 2) + dp * 8;
                float o0 = acc[mt][nt][dp * 2 + 0] + b0;
                float o1 = acc[mt][nt][dp * 2 + 1] + b1;
                if (MODE == 1) { o0 = gelu_exact(o0); o1 = gelu_exact(o1); }
                if (MODE == 2) {
                    const float2 rv = *(const float2*)(res + (size_t)row * N + col);
                    o0 += rv.x; o1 += rv.y;
                }
                float2 ov; ov.x = o0; ov.y = o1;
                *(float2*)(C + (size_t)row * N + col) = ov;
            }
        }
    }
}

// =====================================================================
// HMMA flash attention. CTA = (b, head) x 128 queries, 256 threads.
// (unchanged from R4 — measured fast)
// =====================================================================
#define ATT_SMEM (16384 + 34816 + 256)

__global__ void __launch_bounds__(256, 1)
attn_mma(const float* __restrict__ qkv, float* __restrict__ o)
{
    extern __shared__ char dynsm[];
    __shared__ float smax[2][128];
    __shared__ float lsum2[2][128];

    const uint32_t Qb = smem_u32(dynsm);
    const uint32_t Kb = Qb + 16384u;
    const uint32_t Vb = Kb + 16384u;
    float* Obuf = (float*)(dynsm + 16384);

    const int tid  = threadIdx.x;
    const int lane = tid & 31, wid = tid >> 5;
    const int mg = wid >> 1, kh = wid & 1;
    const int b = blockIdx.x >> 4, hh = blockIdx.x & 15;
    const int q0 = blockIdx.y * 128;
    const size_t tb = (size_t)b * SEQ;
    const size_t RS = 3 * EMB;
    const unsigned FULL = 0xffffffffu;

    {
        const int r = tid >> 1, c0 = (tid & 1) * 32;
        const float* qp = qkv + (tb + q0 + r) * RS + hh * HD + c0;
#pragma unroll
        for (int j = 0; j < 8; ++j) {
            float4 v = *(const float4*)(qp + j * 4);
            __half2 h0 = __floats2half2_rn(v.x * 0.125f, v.y * 0.125f);
            __half2 h1 = __floats2half2_rn(v.z * 0.125f, v.w * 0.125f);
            sts64(Qb + sw128((uint32_t)(r * 128 + (c0 + j * 4) * 2)), h2u(h0), h2u(h1));
        }
    }
    __syncthreads();

    uint32_t QF[2][4][4];
    {
        const int g = lane >> 3;
#pragma unroll
        for (int mt = 0; mt < 2; ++mt)
#pragma unroll
            for (int t = 0; t < 4; ++t) {
                const int r = mg * 32 + mt * 16 + (g & 1) * 8 + (lane & 7);
                const int cb = t * 32 + (g >> 1) * 16;
                ldsm_x4(Qb + sw128((uint32_t)(r * 128 + cb)), QF[mt][t]);
            }
    }

    float Oa[2][8][4];
#pragma unroll
    for (int mt = 0; mt < 2; ++mt)
#pragma unroll
        for (int nt = 0; nt < 8; ++nt)
#pragma unroll
            for (int c = 0; c < 4; ++c) Oa[mt][nt][c] = 0.f;
    float m_run[4], l_run[4];
#pragma unroll
    for (int ri = 0; ri < 4; ++ri) { m_run[ri] = -INFINITY; l_run[ri] = 0.f; }

    for (int kt = 0; kt < SEQ / 128; ++kt) {
        __syncthreads();
        {
            const int r = tid >> 1, c0 = (tid & 1) * 32;
            const float* kp = qkv + (tb + kt * 128 + r) * RS + EMB + hh * HD + c0;
            const float* vp = kp + EMB;
#pragma unroll
            for (int j = 0; j < 8; ++j) {
                float4 kv = *(const float4*)(kp + j * 4);
                float4 vv = *(const float4*)(vp + j * 4);
                uint32_t off = sw128((uint32_t)(r * 128 + (c0 + j * 4) * 2));
                sts64(Kb + off, h2u(__floats2half2_rn(kv.x, kv.y)),
                                h2u(__floats2half2_rn(kv.z, kv.w)));
                sts64(Vb + off, h2u(__floats2half2_rn(vv.x, vv.y)),
                                h2u(__floats2half2_rn(vv.z, vv.w)));
            }
        }
        __syncthreads();

        float sacc[2][8][4];
#pragma unroll
        for (int mt = 0; mt < 2; ++mt)
#pragma unroll
            for (int nt = 0; nt < 8; ++nt)
#pragma unroll
                for (int c = 0; c < 4; ++c) sacc[mt][nt][c] = 0.f;

        const int g = lane >> 3;
#pragma unroll
        for (int t = 0; t < 4; ++t) {
#pragma unroll
            for (int pr = 0; pr < 4; ++pr) {
                const int r = kh * 64 + pr * 16 + (g >> 1) * 8 + (lane & 7);
                const int cb = t * 32 + (g & 1) * 16;
                uint32_t tt[4];
                ldsm_x4(Kb + sw128((uint32_t)(r * 128 + cb)), tt);
#pragma unroll
                for (int mt = 0; mt < 2; ++mt) {
                    mma16816(sacc[mt][pr * 2 + 0], QF[mt][t], tt);
                    mma16816(sacc[mt][pr * 2 + 1], QF[mt][t], tt + 2);
                }
            }
        }

        float mloc[4];
#pragma unroll
        for (int ri = 0; ri < 4; ++ri) {
            const int mt = ri >> 1, h = ri & 1;
            float mx = sacc[mt][0][h * 2];
#pragma unroll
            for (int nt = 0; nt < 8; ++nt) {
                mx = fmaxf(mx, sacc[mt][nt][h * 2]);
                mx = fmaxf(mx, sacc[mt][nt][h * 2 + 1]);
            }
            mx = fmaxf(mx, __shfl_xor_sync(FULL, mx, 1));
            mx = fmaxf(mx, __shfl_xor_sync(FULL, mx, 2));
            mloc[ri] = mx;
        }
        if ((lane & 3) == 0) {
#pragma unroll
            for (int ri = 0; ri < 4; ++ri) {
                const int row = mg * 32 + (ri >> 1) * 16 + (ri & 1) * 8 + (lane >> 2);
                smax[kh][row] = mloc[ri];
            }
        }
        __syncthreads();

        float fexp[4];
#pragma unroll
        for (int ri = 0; ri < 4; ++ri) {
            const int row = mg * 32 + (ri >> 1) * 16 + (ri & 1) * 8 + (lane >> 2);
            const float mk = fmaxf(smax[0][row], smax[1][row]);
            const float mn = fmaxf(m_run[ri], mk);
            fexp[ri] = __expf(m_run[ri] - mn);
            m_run[ri] = mn;
            l_run[ri] *= fexp[ri];
        }
#pragma unroll
        for (int mt = 0; mt < 2; ++mt)
#pragma unroll
            for (int nt = 0; nt < 8; ++nt)
#pragma unroll
                for (int c = 0; c < 4; ++c) {
                    const int ri = mt * 2 + (c >> 1);
                    float p = __expf(sacc[mt][nt][c] - m_run[ri]);
                    sacc[mt][nt][c] = p;
                    l_run[ri] += p;
                }
#pragma unroll
        for (int mt = 0; mt < 2; ++mt)
#pragma unroll
            for (int nt = 0; nt < 8; ++nt)
#pragma unroll
                for (int c = 0; c < 4; ++c)
                    Oa[mt][nt][c] *= fexp[mt * 2 + (c >> 1)];

#pragma unroll
        for (int k2 = 0; k2 < 4; ++k2) {
            uint32_t pa[2][4];
#pragma unroll
            for (int mt = 0; mt < 2; ++mt) {
                pa[mt][0] = h2u(__floats2half2_rn(sacc[mt][2 * k2][0],     sacc[mt][2 * k2][1]));
                pa[mt][1] = h2u(__floats2half2_rn(sacc[mt][2 * k2][2],     sacc[mt][2 * k2][3]));
                pa[mt][2] = h2u(__floats2half2_rn(sacc[mt][2 * k2 + 1][0], sacc[mt][2 * k2 + 1][1]));
                pa[mt][3] = h2u(__floats2half2_rn(sacc[mt][2 * k2 + 1][2], sacc[mt][2 * k2 + 1][3]));
            }
#pragma unroll
            for (int npr = 0; npr < 4; ++npr) {
                const int r = kh * 64 + k2 * 16 + (g & 1) * 8 + (lane & 7);
                const int cb = npr * 32 + (g >> 1) * 16;
                uint32_t tt[4];
                ldsm_x4_t(Vb + sw128((uint32_t)(r * 128 + cb)), tt);
#pragma unroll
                for (int mt = 0; mt < 2; ++mt) {
                    mma16816(Oa[mt][npr * 2 + 0], pa[mt], tt);
                    mma16816(Oa[mt][npr * 2 + 1], pa[mt], tt + 2);
                }
            }
        }
    }

#pragma unroll
    for (int ri = 0; ri < 4; ++ri) {
        l_run[ri] += __shfl_xor_sync(FULL, l_run[ri], 1);
        l_run[ri] += __shfl_xor_sync(FULL, l_run[ri], 2);
    }
    if ((lane & 3) == 0) {
#pragma unroll
        for (int ri = 0; ri < 4; ++ri) {
            const int row = mg * 32 + (ri >> 1) * 16 + (ri & 1) * 8 + (lane >> 2);
            lsum2[kh][row] = l_run[ri];
        }
    }
    __syncthreads();

    if (kh == 0) {
#pragma unroll
        for (int mt = 0; mt < 2; ++mt)
#pragma unroll
            for (int nt = 0; nt < 8; ++nt)
#pragma unroll
                for (int h = 0; h < 2; ++h) {
                    const int row = mg * 32 + mt * 16 + h * 8 + (lane >> 2);
                    const int col = nt * 8 + (lane & 3) * 2;
                    float2 v; v.x = Oa[mt][nt][h * 2]; v.y = Oa[mt][nt][h * 2 + 1];
                    *(float2*)&Obuf[row * 68 + col] = v;
                }
    }
    __syncthreads();
    if (kh == 1) {
#pragma unroll
        for (int mt = 0; mt < 2; ++mt)
#pragma unroll
            for (int h = 0; h < 2; ++h) {
                const int row = mg * 32 + mt * 16 + h * 8 + (lane >> 2);
                const float inv = 1.f / (lsum2[0][row] + lsum2[1][row]);
#pragma unroll
                for (int nt = 0; nt < 8; ++nt) {
                    const int col = nt * 8 + (lane & 3) * 2;
                    const float2 pv = *(const float2*)&Obuf[row * 68 + col];
                    float2 ov;
                    ov.x = (Oa[mt][nt][h * 2 + 0] + pv.x) * inv;
                    ov.y = (Oa[mt][nt][h * 2 + 1] + pv.y) * inv;
                    *(float2*)(o + (tb + q0 + row) * EMB + hh * HD + col) = ov;
                }
            }
    }
}

// ---------------- LayerNorm ----------------
__global__ void ln_kernel(const float* __restrict__ in, float* __restrict__ out,
                          const float* __restrict__ gam, const float* __restrict__ bet)
{
    __shared__ float red[32], red2[32];
    __shared__ float s_mu, s_rstd;
    const int row = blockIdx.x;
    const float* x = in + (size_t)row * EMB;
    float* y = out + (size_t)row * EMB;
    const int tid = threadIdx.x;

    float v[4];
    float s = 0.f, sq = 0.f;
#pragma unroll
    for (int i = 0; i < 4; ++i) {
        v[i] = x[tid + i * 256];
        s += v[i]; sq += v[i] * v[i];
    }
    const unsigned FULL = 0xffffffffu;
#pragma unroll
    for (int o = 16; o > 0; o >>= 1) {
        s  += __shfl_down_sync(FULL, s, o);
        sq += __shfl_down_sync(FULL, sq, o);
    }
    int warp = tid >> 5, lane = tid & 31;
    if (lane == 0) { red[warp] = s; red2[warp] = sq; }
    __syncthreads();
    if (warp == 0) {
        s  = (lane < 8) ? red[lane]  : 0.f;
        sq = (lane < 8) ? red2[lane] : 0.f;
#pragma unroll
        for (int o = 4; o > 0; o >>= 1) {
            s  += __shfl_down_sync(FULL, s, o);
            sq += __shfl_down_sync(FULL, sq, o);
        }
        if (lane == 0) {
            float mu = s * (1.f / EMB);
            float var = sq * (1.f / EMB) - mu * mu;
            s_mu = mu; s_rstd = rsqrtf(var + LN_EPS);
        }
    }
    __syncthreads();
    float mu = s_mu, rstd = s_rstd;
#pragma unroll
    for (int i = 0; i < 4; ++i) {
        int c = tid + i * 256;
        y[c] = (v[i] - mu) * rstd * gam[c] + bet[c];
    }
}

// ---------------- launch ----------------
extern "C" void kernel_launch(void* const* d_in, const int* in_sizes, int n_in,
                              void* d_out, int out_size)
{
    const float* x      = (const float*)d_in[0];
    const float* ln1_g  = (const float*)d_in[1];
    const float* ln1_b  = (const float*)d_in[2];
    const float* ln2_g  = (const float*)d_in[3];
    const float* ln2_b  = (const float*)d_in[4];
    const float* w_qkv  = (const float*)d_in[5];
    const float* b_qkv  = (const float*)d_in[6];
    const float* w_proj = (const float*)d_in[7];
    const float* b_proj = (const float*)d_in[8];
    const float* w_fc1  = (const float*)d_in[9];
    const float* b_fc1  = (const float*)d_in[10];
    const float* w_fc2  = (const float*)d_in[11];
    const float* b_fc2  = (const float*)d_in[12];
    float* out = (float*)d_out;

    void *p_h, *p_qkv, *p_o, *p_x1, *p_act;
    cudaGetSymbolAddress(&p_h, g_h);
    cudaGetSymbolAddress(&p_qkv, g_qkv);
    cudaGetSymbolAddress(&p_o, g_o);
    cudaGetSymbolAddress(&p_x1, g_x1);
    cudaGetSymbolAddress(&p_act, g_act);
    float* h   = (float*)p_h;
    float* qkv = (float*)p_qkv;
    float* o   = (float*)p_o;
    float* x1  = (float*)p_x1;
    float* act = (float*)p_act;

    cudaFuncSetAttribute(mma_gemm<0>, cudaFuncAttributeMaxDynamicSharedMemorySize, GEMM_SMEM);
    cudaFuncSetAttribute(mma_gemm<1>, cudaFuncAttributeMaxDynamicSharedMemorySize, GEMM_SMEM);
    cudaFuncSetAttribute(mma_gemm<2>, cudaFuncAttributeMaxDynamicSharedMemorySize, GEMM_SMEM);
    cudaFuncSetAttribute(attn_mma, cudaFuncAttributeMaxDynamicSharedMemorySize, ATT_SMEM);

    ln_kernel<<<TOK, 256>>>(x, h, ln1_g, ln1_b);
    mma_gemm<0><<<dim3(3 * EMB / 128, TOK / 256), 256, GEMM_SMEM>>>(
        h, w_qkv, b_qkv, nullptr, qkv, TOK, 3 * EMB, EMB);
    attn_mma<<<dim3(2 * NH, SEQ / 128), 256, ATT_SMEM>>>(qkv, o);
    mma_gemm<2><<<dim3(EMB / 128, TOK / 256), 256, GEMM_SMEM>>>(
        o, w_proj, b_proj, x, x1, TOK, EMB, EMB);
    ln_kernel<<<TOK, 256>>>(x1, h, ln2_g, ln2_b);
    mma_gemm<1><<<dim3(MLP / 128, TOK / 256), 256, GEMM_SMEM>>>(
        h, w_fc1, b_fc1, nullptr, act, TOK, MLP, EMB);
    mma_gemm<2><<<dim3(EMB / 128, TOK / 256), 256, GEMM_SMEM>>>(
        act, w_fc2, b_fc2, x1, out, TOK, EMB, MLP);
}

// round 6
// speedup vs baseline: 9.0642x; 1.1199x over previous
#include <cuda_runtime.h>
#include <cuda_fp16.h>
#include <math.h>
#include <stdint.h>

// ---------------- problem constants ----------------
#define TOK   4096
#define EMB   1024
#define NH    16
#define HD    64
#define SEQ   2048
#define MLP   4096
#define LN_EPS 1e-5f

// ---------------- scratch ----------------
static __device__ float g_h  [(size_t)TOK * EMB];
static __device__ float g_qkv[(size_t)TOK * 3 * EMB];
static __device__ float g_o  [(size_t)TOK * EMB];
static __device__ float g_x1 [(size_t)TOK * EMB];
static __device__ float g_act[(size_t)TOK * MLP];

// ---------------- helpers ----------------
__device__ __forceinline__ uint32_t smem_u32(const void* p) {
    uint32_t a;
    asm("{ .reg .u64 t; cvta.to.shared.u64 t, %1; cvt.u32.u64 %0, t; }" : "=r"(a) : "l"(p));
    return a;
}
__device__ __forceinline__ void sts64(uint32_t addr, uint32_t a, uint32_t b) {
    asm volatile("st.shared.v2.b32 [%0], {%1, %2};" :: "r"(addr), "r"(a), "r"(b));
}
__device__ __forceinline__ uint32_t h2u(__half2 h) { return *(uint32_t*)&h; }
// swizzle for 64-byte rows (GEMM): 16B chunk bits [4:6) ^= (row>>1)&3
__device__ __forceinline__ uint32_t swz(uint32_t off) {
    return off ^ (((off >> 7) & 3u) << 4);
}
// swizzle for 128-byte rows (attention): 16B chunk bits [4:7) ^= row&7
__device__ __forceinline__ uint32_t sw128(uint32_t off) {
    return off ^ ((off >> 3) & 0x70u);
}
__device__ __forceinline__ void ldsm_x4(uint32_t addr, uint32_t* r) {
    asm volatile("ldmatrix.sync.aligned.m8n8.x4.shared.b16 {%0,%1,%2,%3}, [%4];"
        : "=r"(r[0]), "=r"(r[1]), "=r"(r[2]), "=r"(r[3]) : "r"(addr));
}
__device__ __forceinline__ void ldsm_x4_t(uint32_t addr, uint32_t* r) {
    asm volatile("ldmatrix.sync.aligned.m8n8.x4.trans.shared.b16 {%0,%1,%2,%3}, [%4];"
        : "=r"(r[0]), "=r"(r[1]), "=r"(r[2]), "=r"(r[3]) : "r"(addr));
}
__device__ __forceinline__ void mma16816(float* d, const uint32_t* a, const uint32_t* b) {
    asm volatile("mma.sync.aligned.m16n8k16.row.col.f32.f16.f16.f32 "
        "{%0,%1,%2,%3}, {%4,%5,%6,%7}, {%8,%9}, {%0,%1,%2,%3};"
        : "+f"(d[0]), "+f"(d[1]), "+f"(d[2]), "+f"(d[3])
        : "r"(a[0]), "r"(a[1]), "r"(a[2]), "r"(a[3]), "r"(b[0]), "r"(b[1]));
}
__device__ __forceinline__ float gelu_exact(float x) {
    return 0.5f * x * (1.f + erff(x * 0.70710678118654752f));
}

// =====================================================================
// HMMA GEMM: A fp16 (single), B fp16 hi/lo split (2 mma terms).
// Block tile 128x128, BK=32, 8 warps (2M x 4N) of 64x32 each.
// Double-buffered smem: A 8KB | Bhi 8KB | Blo 8KB => 24KB/buf, 48KB total.
// MODE: 0 = bias, 1 = bias+gelu, 2 = bias+res
// =====================================================================
#define GEMM_SMEM (2 * 24576)

template<int MODE>
__global__ void __launch_bounds__(256, 2)
mma_gemm(const float* __restrict__ A, const float* __restrict__ B,
         const float* __restrict__ bias, const float* __restrict__ res,
         float* __restrict__ C, int M, int N, int K)
{
    extern __shared__ char dsm[];
    const uint32_t base = smem_u32(dsm);

    const int tid  = threadIdx.x;
    const int lane = tid & 31, wid = tid >> 5;
    const int wm = (wid & 1) * 64;
    const int wn = (wid >> 1) * 32;
    const int bm = blockIdx.y * 128, bn = blockIdx.x * 128;

    const int am  = tid >> 1;             // A row 0..127
    const int ak  = (tid & 1) * 16;       // A k start (16 floats)
    const int bk  = (tid & 7) * 4;        // B k start (4 rows)
    const int bnq = (tid >> 3) * 4;       // B n start (4 cols)

    const float* Ap = A + (size_t)(bm + am) * K + ak;
    const float* Bp = B + (size_t)bk * N + bn + bnq;

    float acc[4][4][4];
#pragma unroll
    for (int i = 0; i < 4; ++i)
#pragma unroll
        for (int j = 0; j < 4; ++j)
#pragma unroll
            for (int c = 0; c < 4; ++c) acc[i][j][c] = 0.f;

    const int nch = K / 32;
    float4 bufA[4], bufB[4];

    auto ldgA = [&](int kc) {
#pragma unroll
        for (int j = 0; j < 4; ++j)
            bufA[j] = *(const float4*)(Ap + kc * 32 + j * 4);
    };
    auto ldgB = [&](int kc) {
#pragma unroll
        for (int j = 0; j < 4; ++j)
            bufB[j] = *(const float4*)(Bp + (size_t)(kc * 32 + j) * N);
    };
    auto stsA = [&](int buf) {
        const uint32_t sA = base + buf * 24576u;
#pragma unroll
        for (int j = 0; j < 4; ++j) {
            float4 v = bufA[j];
            __half2 h0 = __floats2half2_rn(v.x, v.y);
            __half2 h1 = __floats2half2_rn(v.z, v.w);
            sts64(sA + swz((uint32_t)(am * 64 + (ak + j * 4) * 2)), h2u(h0), h2u(h1));
        }
    };
    auto stsB = [&](int buf) {
        const uint32_t sBhi = base + buf * 24576u + 8192u;
        const uint32_t sBlo = sBhi + 8192u;
        float vk[4][4];
#pragma unroll
        for (int j = 0; j < 4; ++j) {
            vk[j][0] = bufB[j].x; vk[j][1] = bufB[j].y;
            vk[j][2] = bufB[j].z; vk[j][3] = bufB[j].w;
        }
#pragma unroll
        for (int i = 0; i < 4; ++i) {
            __half2 h01 = __floats2half2_rn(vk[0][i], vk[1][i]);
            __half2 h23 = __floats2half2_rn(vk[2][i], vk[3][i]);
            float2 f01 = __half22float2(h01);
            float2 f23 = __half22float2(h23);
            __half2 l01 = __floats2half2_rn(vk[0][i] - f01.x, vk[1][i] - f01.y);
            __half2 l23 = __floats2half2_rn(vk[2][i] - f23.x, vk[3][i] - f23.y);
            uint32_t off = swz((uint32_t)((bnq + i) * 64 + bk * 2));
            sts64(sBhi + off, h2u(h01), h2u(h23));
            sts64(sBlo + off, h2u(l01), h2u(l23));
        }
    };

    auto ldA = [&](uint32_t sa, int ks, uint32_t AF[4][4]) {
        const int g = lane >> 3;
        const int r = wm + (g & 1) * 8 + (lane & 7);
        const int cb = ks * 32 + (g >> 1) * 16;
#pragma unroll
        for (int mt = 0; mt < 4; ++mt)
            ldsm_x4(sa + swz((uint32_t)((r + mt * 16) * 64 + cb)), AF[mt]);
    };
    auto ldB = [&](uint32_t sb, int ks, uint32_t BF[4][2]) {
        const int g = lane >> 3;
        const int r = wn + (g >> 1) * 8 + (lane & 7);
        const int cb = ks * 32 + (g & 1) * 16;
        uint32_t t[4];
        ldsm_x4(sb + swz((uint32_t)(r * 64 + cb)), t);
        BF[0][0] = t[0]; BF[0][1] = t[1]; BF[1][0] = t[2]; BF[1][1] = t[3];
        ldsm_x4(sb + swz((uint32_t)((r + 16) * 64 + cb)), t);
        BF[2][0] = t[0]; BF[2][1] = t[1]; BF[3][0] = t[2]; BF[3][1] = t[3];
    };
    auto mmaAll = [&](uint32_t AF[4][4], uint32_t BF[4][2]) {
#pragma unroll
        for (int mt = 0; mt < 4; ++mt)
#pragma unroll
            for (int nt = 0; nt < 4; ++nt)
                mma16816(acc[mt][nt], AF[mt], BF[nt]);
    };
    auto compute = [&](int buf) {
        const uint32_t sA   = base + buf * 24576u;
        const uint32_t sBhi = sA + 8192u;
        const uint32_t sBlo = sA + 16384u;
#pragma unroll
        for (int ks = 0; ks < 2; ++ks) {
            uint32_t AF[4][4], BF[4][2];
            ldA(sA, ks, AF);           // A fragments, reused for both terms
            ldB(sBhi, ks, BF);
            mmaAll(AF, BF);            // A * Bhi
            ldB(sBlo, ks, BF);
            mmaAll(AF, BF);            // A * Blo
        }
    };

    ldgA(0); stsA(0);
    ldgB(0); stsB(0);
    __syncthreads();

    for (int kc = 0; kc < nch; ++kc) {
        const int cur = kc & 1;
        const bool more = (kc + 1 < nch);
        if (more) ldgA(kc + 1);
        compute(cur);
        if (more) {
            stsA(cur ^ 1);
            ldgB(kc + 1);
            stsB(cur ^ 1);
        }
        __syncthreads();
    }

    // ---- epilogue ----
#pragma unroll
    for (int mt = 0; mt < 4; ++mt) {
#pragma unroll
        for (int nt = 0; nt < 4; ++nt) {
            const int col = bn + wn + nt * 8 + (lane & 3) * 2;
            const float b0 = bias[col], b1 = bias[col + 1];
#pragma unroll
            for (int dp = 0; dp < 2; ++dp) {
                const int row = bm + wm + mt * 16 + (lane >> 2) + dp * 8;
                float o0 = acc[mt][nt][dp * 2 + 0] + b0;
                float o1 = acc[mt][nt][dp * 2 + 1] + b1;
                if (MODE == 1) { o0 = gelu_exact(o0); o1 = gelu_exact(o1); }
                if (MODE == 2) {
                    const float2 rv = *(const float2*)(res + (size_t)row * N + col);
                    o0 += rv.x; o1 += rv.y;
                }
                float2 ov; ov.x = o0; ov.y = o1;
                *(float2*)(C + (size_t)row * N + col) = ov;
            }
        }
    }
}

// =====================================================================
// HMMA flash attention. CTA = (b, head) x 128 queries, 256 threads.
// (unchanged — measured fast)
// =====================================================================
#define ATT_SMEM (16384 + 34816 + 256)

__global__ void __launch_bounds__(256, 1)
attn_mma(const float* __restrict__ qkv, float* __restrict__ o)
{
    extern __shared__ char dynsm[];
    __shared__ float smax[2][128];
    __shared__ float lsum2[2][128];

    const uint32_t Qb = smem_u32(dynsm);
    const uint32_t Kb = Qb + 16384u;
    const uint32_t Vb = Kb + 16384u;
    float* Obuf = (float*)(dynsm + 16384);

    const int tid  = threadIdx.x;
    const int lane = tid & 31, wid = tid >> 5;
    const int mg = wid >> 1, kh = wid & 1;
    const int b = blockIdx.x >> 4, hh = blockIdx.x & 15;
    const int q0 = blockIdx.y * 128;
    const size_t tb = (size_t)b * SEQ;
    const size_t RS = 3 * EMB;
    const unsigned FULL = 0xffffffffu;

    {
        const int r = tid >> 1, c0 = (tid & 1) * 32;
        const float* qp = qkv + (tb + q0 + r) * RS + hh * HD + c0;
#pragma unroll
        for (int j = 0; j < 8; ++j) {
            float4 v = *(const float4*)(qp + j * 4);
            __half2 h0 = __floats2half2_rn(v.x * 0.125f, v.y * 0.125f);
            __half2 h1 = __floats2half2_rn(v.z * 0.125f, v.w * 0.125f);
            sts64(Qb + sw128((uint32_t)(r * 128 + (c0 + j * 4) * 2)), h2u(h0), h2u(h1));
        }
    }
    __syncthreads();

    uint32_t QF[2][4][4];
    {
        const int g = lane >> 3;
#pragma unroll
        for (int mt = 0; mt < 2; ++mt)
#pragma unroll
            for (int t = 0; t < 4; ++t) {
                const int r = mg * 32 + mt * 16 + (g & 1) * 8 + (lane & 7);
                const int cb = t * 32 + (g >> 1) * 16;
                ldsm_x4(Qb + sw128((uint32_t)(r * 128 + cb)), QF[mt][t]);
            }
    }

    float Oa[2][8][4];
#pragma unroll
    for (int mt = 0; mt < 2; ++mt)
#pragma unroll
        for (int nt = 0; nt < 8; ++nt)
#pragma unroll
            for (int c = 0; c < 4; ++c) Oa[mt][nt][c] = 0.f;
    float m_run[4], l_run[4];
#pragma unroll
    for (int ri = 0; ri < 4; ++ri) { m_run[ri] = -INFINITY; l_run[ri] = 0.f; }

    for (int kt = 0; kt < SEQ / 128; ++kt) {
        __syncthreads();
        {
            const int r = tid >> 1, c0 = (tid & 1) * 32;
            const float* kp = qkv + (tb + kt * 128 + r) * RS + EMB + hh * HD + c0;
            const float* vp = kp + EMB;
#pragma unroll
            for (int j = 0; j < 8; ++j) {
                float4 kv = *(const float4*)(kp + j * 4);
                float4 vv = *(const float4*)(vp + j * 4);
                uint32_t off = sw128((uint32_t)(r * 128 + (c0 + j * 4) * 2));
                sts64(Kb + off, h2u(__floats2half2_rn(kv.x, kv.y)),
                                h2u(__floats2half2_rn(kv.z, kv.w)));
                sts64(Vb + off, h2u(__floats2half2_rn(vv.x, vv.y)),
                                h2u(__floats2half2_rn(vv.z, vv.w)));
            }
        }
        __syncthreads();

        float sacc[2][8][4];
#pragma unroll
        for (int mt = 0; mt < 2; ++mt)
#pragma unroll
            for (int nt = 0; nt < 8; ++nt)
#pragma unroll
                for (int c = 0; c < 4; ++c) sacc[mt][nt][c] = 0.f;

        const int g = lane >> 3;
#pragma unroll
        for (int t = 0; t < 4; ++t) {
#pragma unroll
            for (int pr = 0; pr < 4; ++pr) {
                const int r = kh * 64 + pr * 16 + (g >> 1) * 8 + (lane & 7);
                const int cb = t * 32 + (g & 1) * 16;
                uint32_t tt[4];
                ldsm_x4(Kb + sw128((uint32_t)(r * 128 + cb)), tt);
#pragma unroll
                for (int mt = 0; mt < 2; ++mt) {
                    mma16816(sacc[mt][pr * 2 + 0], QF[mt][t], tt);
                    mma16816(sacc[mt][pr * 2 + 1], QF[mt][t], tt + 2);
                }
            }
        }

        float mloc[4];
#pragma unroll
        for (int ri = 0; ri < 4; ++ri) {
            const int mt = ri >> 1, h = ri & 1;
            float mx = sacc[mt][0][h * 2];
#pragma unroll
            for (int nt = 0; nt < 8; ++nt) {
                mx = fmaxf(mx, sacc[mt][nt][h * 2]);
                mx = fmaxf(mx, sacc[mt][nt][h * 2 + 1]);
            }
            mx = fmaxf(mx, __shfl_xor_sync(FULL, mx, 1));
            mx = fmaxf(mx, __shfl_xor_sync(FULL, mx, 2));
            mloc[ri] = mx;
        }
        if ((lane & 3) == 0) {
#pragma unroll
            for (int ri = 0; ri < 4; ++ri) {
                const int row = mg * 32 + (ri >> 1) * 16 + (ri & 1) * 8 + (lane >> 2);
                smax[kh][row] = mloc[ri];
            }
        }
        __syncthreads();

        float fexp[4];
#pragma unroll
        for (int ri = 0; ri < 4; ++ri) {
            const int row = mg * 32 + (ri >> 1) * 16 + (ri & 1) * 8 + (lane >> 2);
            const float mk = fmaxf(smax[0][row], smax[1][row]);
            const float mn = fmaxf(m_run[ri], mk);
            fexp[ri] = __expf(m_run[ri] - mn);
            m_run[ri] = mn;
            l_run[ri] *= fexp[ri];
        }
#pragma unroll
        for (int mt = 0; mt < 2; ++mt)
#pragma unroll
            for (int nt = 0; nt < 8; ++nt)
#pragma unroll
                for (int c = 0; c < 4; ++c) {
                    const int ri = mt * 2 + (c >> 1);
                    float p = __expf(sacc[mt][nt][c] - m_run[ri]);
                    sacc[mt][nt][c] = p;
                    l_run[ri] += p;
                }
#pragma unroll
        for (int mt = 0; mt < 2; ++mt)
#pragma unroll
            for (int nt = 0; nt < 8; ++nt)
#pragma unroll
                for (int c = 0; c < 4; ++c)
                    Oa[mt][nt][c] *= fexp[mt * 2 + (c >> 1)];

#pragma unroll
        for (int k2 = 0; k2 < 4; ++k2) {
            uint32_t pa[2][4];
#pragma unroll
            for (int mt = 0; mt < 2; ++mt) {
                pa[mt][0] = h2u(__floats2half2_rn(sacc[mt][2 * k2][0],     sacc[mt][2 * k2][1]));
                pa[mt][1] = h2u(__floats2half2_rn(sacc[mt][2 * k2][2],     sacc[mt][2 * k2][3]));
                pa[mt][2] = h2u(__floats2half2_rn(sacc[mt][2 * k2 + 1][0], sacc[mt][2 * k2 + 1][1]));
                pa[mt][3] = h2u(__floats2half2_rn(sacc[mt][2 * k2 + 1][2], sacc[mt][2 * k2 + 1][3]));
            }
#pragma unroll
            for (int npr = 0; npr < 4; ++npr) {
                const int r = kh * 64 + k2 * 16 + (g & 1) * 8 + (lane & 7);
                const int cb = npr * 32 + (g >> 1) * 16;
                uint32_t tt[4];
                ldsm_x4_t(Vb + sw128((uint32_t)(r * 128 + cb)), tt);
#pragma unroll
                for (int mt = 0; mt < 2; ++mt) {
                    mma16816(Oa[mt][npr * 2 + 0], pa[mt], tt);
                    mma16816(Oa[mt][npr * 2 + 1], pa[mt], tt + 2);
                }
            }
        }
    }

#pragma unroll
    for (int ri = 0; ri < 4; ++ri) {
        l_run[ri] += __shfl_xor_sync(FULL, l_run[ri], 1);
        l_run[ri] += __shfl_xor_sync(FULL, l_run[ri], 2);
    }
    if ((lane & 3) == 0) {
#pragma unroll
        for (int ri = 0; ri < 4; ++ri) {
            const int row = mg * 32 + (ri >> 1) * 16 + (ri & 1) * 8 + (lane >> 2);
            lsum2[kh][row] = l_run[ri];
        }
    }
    __syncthreads();

    if (kh == 0) {
#pragma unroll
        for (int mt = 0; mt < 2; ++mt)
#pragma unroll
            for (int nt = 0; nt < 8; ++nt)
#pragma unroll
                for (int h = 0; h < 2; ++h) {
                    const int row = mg * 32 + mt * 16 + h * 8 + (lane >> 2);
                    const int col = nt * 8 + (lane & 3) * 2;
                    float2 v; v.x = Oa[mt][nt][h * 2]; v.y = Oa[mt][nt][h * 2 + 1];
                    *(float2*)&Obuf[row * 68 + col] = v;
                }
    }
    __syncthreads();
    if (kh == 1) {
#pragma unroll
        for (int mt = 0; mt < 2; ++mt)
#pragma unroll
            for (int h = 0; h < 2; ++h) {
                const int row = mg * 32 + mt * 16 + h * 8 + (lane >> 2);
                const float inv = 1.f / (lsum2[0][row] + lsum2[1][row]);
#pragma unroll
                for (int nt = 0; nt < 8; ++nt) {
                    const int col = nt * 8 + (lane & 3) * 2;
                    const float2 pv = *(const float2*)&Obuf[row * 68 + col];
                    float2 ov;
                    ov.x = (Oa[mt][nt][h * 2 + 0] + pv.x) * inv;
                    ov.y = (Oa[mt][nt][h * 2 + 1] + pv.y) * inv;
                    *(float2*)(o + (tb + q0 + row) * EMB + hh * HD + col) = ov;
                }
            }
    }
}

// ---------------- LayerNorm ----------------
__global__ void ln_kernel(const float* __restrict__ in, float* __restrict__ out,
                          const float* __restrict__ gam, const float* __restrict__ bet)
{
    __shared__ float red[32], red2[32];
    __shared__ float s_mu, s_rstd;
    const int row = blockIdx.x;
    const float* x = in + (size_t)row * EMB;
    float* y = out + (size_t)row * EMB;
    const int tid = threadIdx.x;

    float v[4];
    float s = 0.f, sq = 0.f;
#pragma unroll
    for (int i = 0; i < 4; ++i) {
        v[i] = x[tid + i * 256];
        s += v[i]; sq += v[i] * v[i];
    }
    const unsigned FULL = 0xffffffffu;
#pragma unroll
    for (int o = 16; o > 0; o >>= 1) {
        s  += __shfl_down_sync(FULL, s, o);
        sq += __shfl_down_sync(FULL, sq, o);
    }
    int warp = tid >> 5, lane = tid & 31;
    if (lane == 0) { red[warp] = s; red2[warp] = sq; }
    __syncthreads();
    if (warp == 0) {
        s  = (lane < 8) ? red[lane]  : 0.f;
        sq = (lane < 8) ? red2[lane] : 0.f;
#pragma unroll
        for (int o = 4; o > 0; o >>= 1) {
            s  += __shfl_down_sync(FULL, s, o);
            sq += __shfl_down_sync(FULL, sq, o);
        }
        if (lane == 0) {
            float mu = s * (1.f / EMB);
            float var = sq * (1.f / EMB) - mu * mu;
            s_mu = mu; s_rstd = rsqrtf(var + LN_EPS);
        }
    }
    __syncthreads();
    float mu = s_mu, rstd = s_rstd;
#pragma unroll
    for (int i = 0; i < 4; ++i) {
        int c = tid + i * 256;
        y[c] = (v[i] - mu) * rstd * gam[c] + bet[c];
    }
}

// ---------------- launch ----------------
extern "C" void kernel_launch(void* const* d_in, const int* in_sizes, int n_in,
                              void* d_out, int out_size)
{
    const float* x      = (const float*)d_in[0];
    const float* ln1_g  = (const float*)d_in[1];
    const float* ln1_b  = (const float*)d_in[2];
    const float* ln2_g  = (const float*)d_in[3];
    const float* ln2_b  = (const float*)d_in[4];
    const float* w_qkv  = (const float*)d_in[5];
    const float* b_qkv  = (const float*)d_in[6];
    const float* w_proj = (const float*)d_in[7];
    const float* b_proj = (const float*)d_in[8];
    const float* w_fc1  = (const float*)d_in[9];
    const float* b_fc1  = (const float*)d_in[10];
    const float* w_fc2  = (const float*)d_in[11];
    const float* b_fc2  = (const float*)d_in[12];
    float* out = (float*)d_out;

    void *p_h, *p_qkv, *p_o, *p_x1, *p_act;
    cudaGetSymbolAddress(&p_h, g_h);
    cudaGetSymbolAddress(&p_qkv, g_qkv);
    cudaGetSymbolAddress(&p_o, g_o);
    cudaGetSymbolAddress(&p_x1, g_x1);
    cudaGetSymbolAddress(&p_act, g_act);
    float* h   = (float*)p_h;
    float* qkv = (float*)p_qkv;
    float* o   = (float*)p_o;
    float* x1  = (float*)p_x1;
    float* act = (float*)p_act;

    cudaFuncSetAttribute(mma_gemm<0>, cudaFuncAttributeMaxDynamicSharedMemorySize, GEMM_SMEM);
    cudaFuncSetAttribute(mma_gemm<1>, cudaFuncAttributeMaxDynamicSharedMemorySize, GEMM_SMEM);
    cudaFuncSetAttribute(mma_gemm<2>, cudaFuncAttributeMaxDynamicSharedMemorySize, GEMM_SMEM);
    cudaFuncSetAttribute(attn_mma, cudaFuncAttributeMaxDynamicSharedMemorySize, ATT_SMEM);

    ln_kernel<<<TOK, 256>>>(x, h, ln1_g, ln1_b);
    mma_gemm<0><<<dim3(3 * EMB / 128, TOK / 128), 256, GEMM_SMEM>>>(
        h, w_qkv, b_qkv, nullptr, qkv, TOK, 3 * EMB, EMB);
    attn_mma<<<dim3(2 * NH, SEQ / 128), 256, ATT_SMEM>>>(qkv, o);
    mma_gemm<2><<<dim3(EMB / 128, TOK / 128), 256, GEMM_SMEM>>>(
        o, w_proj, b_proj, x, x1, TOK, EMB, EMB);
    ln_kernel<<<TOK, 256>>>(x1, h, ln2_g, ln2_b);
    mma_gemm<1><<<dim3(MLP / 128, TOK / 128), 256, GEMM_SMEM>>>(
        h, w_fc1, b_fc1, nullptr, act, TOK, MLP, EMB);
    mma_gemm<2><<<dim3(EMB / 128, TOK / 128), 256, GEMM_SMEM>>>(
        act, w_fc2, b_fc2, x1, out, TOK, EMB, MLP);
}

// round 7
// speedup vs baseline: 22.2153x; 2.4509x over previous
#include <cuda_runtime.h>
#include <cuda_fp16.h>
#include <math.h>
#include <stdint.h>

// ---------------- problem constants ----------------
#define TOK   4096
#define EMB   1024
#define NH    16
#define HD    64
#define SEQ   2048
#define MLP   4096
#define LN_EPS 1e-5f

// ---------------- scratch ----------------
static __device__ __half g_h16 [(size_t)TOK * EMB];
static __device__ __half g_qkv16[(size_t)TOK * 3 * EMB];
static __device__ __half g_o16 [(size_t)TOK * EMB];
static __device__ __half g_act16[(size_t)TOK * MLP];
static __device__ float  g_x1  [(size_t)TOK * EMB];
static __device__ __half g_wq16[(size_t)EMB * 3 * EMB];
static __device__ __half g_wp16[(size_t)EMB * EMB];
static __device__ __half g_w116[(size_t)EMB * MLP];
static __device__ __half g_w216[(size_t)MLP * EMB];

// ---------------- helpers ----------------
__device__ __forceinline__ uint32_t smem_u32(const void* p) {
    uint32_t a;
    asm("{ .reg .u64 t; cvta.to.shared.u64 t, %1; cvt.u32.u64 %0, t; }" : "=r"(a) : "l"(p));
    return a;
}
__device__ __forceinline__ void sts128(uint32_t addr, uint4 v) {
    asm volatile("st.shared.v4.b32 [%0], {%1, %2, %3, %4};"
        :: "r"(addr), "r"(v.x), "r"(v.y), "r"(v.z), "r"(v.w));
}
__device__ __forceinline__ uint32_t h2u(__half2 h) { return *(uint32_t*)&h; }
// 64B rows: 16B chunk bits [4:6) ^= (row>>1)&3
__device__ __forceinline__ uint32_t swz(uint32_t off) {
    return off ^ (((off >> 7) & 3u) << 4);
}
// 128B rows: 16B chunk bits [4:7) ^= row&7
__device__ __forceinline__ uint32_t sw128(uint32_t off) {
    return off ^ ((off >> 3) & 0x70u);
}
// 256B rows: 16B chunk bits [4:7) ^= row&7
__device__ __forceinline__ uint32_t sw256(uint32_t off) {
    return off ^ (((off >> 8) & 7u) << 4);
}
__device__ __forceinline__ void ldsm_x4(uint32_t addr, uint32_t* r) {
    asm volatile("ldmatrix.sync.aligned.m8n8.x4.shared.b16 {%0,%1,%2,%3}, [%4];"
        : "=r"(r[0]), "=r"(r[1]), "=r"(r[2]), "=r"(r[3]) : "r"(addr));
}
__device__ __forceinline__ void ldsm_x4_t(uint32_t addr, uint32_t* r) {
    asm volatile("ldmatrix.sync.aligned.m8n8.x4.trans.shared.b16 {%0,%1,%2,%3}, [%4];"
        : "=r"(r[0]), "=r"(r[1]), "=r"(r[2]), "=r"(r[3]) : "r"(addr));
}
__device__ __forceinline__ void mma16816(float* d, const uint32_t* a, const uint32_t* b) {
    asm volatile("mma.sync.aligned.m16n8k16.row.col.f32.f16.f16.f32 "
        "{%0,%1,%2,%3}, {%4,%5,%6,%7}, {%8,%9}, {%0,%1,%2,%3};"
        : "+f"(d[0]), "+f"(d[1]), "+f"(d[2]), "+f"(d[3])
        : "r"(a[0]), "r"(a[1]), "r"(a[2]), "r"(a[3]), "r"(b[0]), "r"(b[1]));
}
__device__ __forceinline__ void cpasync16(uint32_t saddr, const void* g) {
    asm volatile("cp.async.cg.shared.global [%0], [%1], 16;" :: "r"(saddr), "l"(g));
}
#define CP_COMMIT() asm volatile("cp.async.commit_group;" ::: "memory")
#define CP_WAIT2()  asm volatile("cp.async.wait_group 2;" ::: "memory")
__device__ __forceinline__ float gelu_exact(float x) {
    return 0.5f * x * (1.f + erff(x * 0.70710678118654752f));
}

// =====================================================================
// fp32 -> fp16 weight conversion (once per launch)
// =====================================================================
__global__ void f2h_kernel(const float* __restrict__ src, __half* __restrict__ dst, int n)
{
    int i = (blockIdx.x * blockDim.x + threadIdx.x) * 8;
    if (i < n) {
        float4 a = *(const float4*)(src + i);
        float4 b = *(const float4*)(src + i + 4);
        uint4 o;
        o.x = h2u(__floats2half2_rn(a.x, a.y));
        o.y = h2u(__floats2half2_rn(a.z, a.w));
        o.z = h2u(__floats2half2_rn(b.x, b.y));
        o.w = h2u(__floats2half2_rn(b.z, b.w));
        *(uint4*)(dst + i) = o;
    }
}

// =====================================================================
// HMMA GEMM, all-fp16 operands, cp.async 4-stage pipeline.
// C[M,N] = epi(A[M,K] @ B[K,N] + bias [, res])
// Block 128x128, BK=32, 8 warps (2M x 4N) of 64x32.
// smem/stage: A [128][32]h (64B rows, swz) 8KB | B [32][128]h (256B rows, sw256) 8KB
// MODE: 0 = bias -> fp16 out, 1 = bias+gelu -> fp16 out, 2 = bias+res -> fp32 out
// =====================================================================
#define GEMM_SMEM (4 * 16384)

template<int MODE>
__global__ void __launch_bounds__(256, 2)
hgemm(const __half* __restrict__ A, const __half* __restrict__ B,
      const float* __restrict__ bias, const float* __restrict__ res,
      void* __restrict__ Cout, int M, int N, int K)
{
    extern __shared__ char dsm[];
    const uint32_t base = smem_u32(dsm);

    const int tid  = threadIdx.x;
    const int lane = tid & 31, wid = tid >> 5;
    const int wm = (wid & 1) * 64;
    const int wn = (wid >> 1) * 32;
    const int bm = blockIdx.y * 128, bn = blockIdx.x * 128;
    const int g = lane >> 3;

    float acc[4][4][4];
#pragma unroll
    for (int i = 0; i < 4; ++i)
#pragma unroll
        for (int j = 0; j < 4; ++j)
#pragma unroll
            for (int c = 0; c < 4; ++c) acc[i][j][c] = 0.f;

    const int nch = K / 32;

    auto issue = [&](int buf, int kc) {
        const uint32_t sA = base + buf * 16384u;
        const uint32_t sB = sA + 8192u;
#pragma unroll
        for (int i = 0; i < 2; ++i) {
            const int cc = tid * 2 + i;
            const int rowa = cc >> 2, kch = cc & 3;
            cpasync16(sA + swz((uint32_t)(rowa * 64 + kch * 16)),
                      A + (size_t)(bm + rowa) * K + kc * 32 + kch * 8);
            const int rowb = cc >> 4, nch2 = cc & 15;
            cpasync16(sB + sw256((uint32_t)(rowb * 256 + nch2 * 16)),
                      B + (size_t)(kc * 32 + rowb) * N + bn + nch2 * 8);
        }
    };

    auto compute = [&](int buf) {
        const uint32_t sA = base + buf * 16384u;
        const uint32_t sB = sA + 8192u;
#pragma unroll
        for (int ks = 0; ks < 2; ++ks) {
            uint32_t AF[4][4];
            const int ra = wm + (g & 1) * 8 + (lane & 7);
            const int ca = ks * 32 + (g >> 1) * 16;
#pragma unroll
            for (int mt = 0; mt < 4; ++mt)
                ldsm_x4(sA + swz((uint32_t)((ra + mt * 16) * 64 + ca)), AF[mt]);
            const int rb = ks * 16 + (g & 1) * 8 + (lane & 7);
#pragma unroll
            for (int p = 0; p < 2; ++p) {
                uint32_t t[4];
                const int cbb = (wn + p * 16) * 2 + (g >> 1) * 16;
                ldsm_x4_t(sB + sw256((uint32_t)(rb * 256 + cbb)), t);
#pragma unroll
                for (int mt = 0; mt < 4; ++mt) {
                    mma16816(acc[mt][p * 2 + 0], AF[mt], t);
                    mma16816(acc[mt][p * 2 + 1], AF[mt], t + 2);
                }
            }
        }
    };

    // prologue: 3 stages in flight
    issue(0, 0); CP_COMMIT();
    issue(1, 1); CP_COMMIT();
    issue(2, 2); CP_COMMIT();

    for (int kc = 0; kc < nch; ++kc) {
        CP_WAIT2();
        __syncthreads();
        compute(kc & 3);
        if (kc + 3 < nch) issue((kc + 3) & 3, kc + 3);
        CP_COMMIT();
    }

    // ---- epilogue ----
#pragma unroll
    for (int mt = 0; mt < 4; ++mt) {
#pragma unroll
        for (int nt = 0; nt < 4; ++nt) {
            const int col = bn + wn + nt * 8 + (lane & 3) * 2;
            const float b0 = bias[col], b1 = bias[col + 1];
#pragma unroll
            for (int dp = 0; dp < 2; ++dp) {
                const int row = bm + wm + mt * 16 + (lane >> 2) + dp * 8;
                float o0 = acc[mt][nt][dp * 2 + 0] + b0;
                float o1 = acc[mt][nt][dp * 2 + 1] + b1;
                if (MODE == 1) { o0 = gelu_exact(o0); o1 = gelu_exact(o1); }
                if (MODE == 2) {
                    const float2 rv = *(const float2*)(res + (size_t)row * N + col);
                    float2 ov; ov.x = o0 + rv.x; ov.y = o1 + rv.y;
                    *(float2*)((float*)Cout + (size_t)row * N + col) = ov;
                } else {
                    *(__half2*)((__half*)Cout + (size_t)row * N + col) =
                        __floats2half2_rn(o0, o1);
                }
            }
        }
    }
}

// =====================================================================
// HMMA flash attention, fp16 in / fp16 out.
// CTA = (b, head) x 128 queries, 256 threads; 8 warps (4 q-groups x 2 key-halves).
// =====================================================================
#define ATT_SMEM (16384 + 34816 + 256)

__global__ void __launch_bounds__(256, 1)
attn_mma(const __half* __restrict__ qkv, __half* __restrict__ o)
{
    extern __shared__ char dynsm[];
    __shared__ float smax[2][128];
    __shared__ float lsum2[2][128];

    const uint32_t Qb = smem_u32(dynsm);
    const uint32_t Kb = Qb + 16384u;
    const uint32_t Vb = Kb + 16384u;
    float* Obuf = (float*)(dynsm + 16384);

    const int tid  = threadIdx.x;
    const int lane = tid & 31, wid = tid >> 5;
    const int mg = wid >> 1, kh = wid & 1;
    const int b = blockIdx.x >> 4, hh = blockIdx.x & 15;
    const int q0 = blockIdx.y * 128;
    const size_t tb = (size_t)b * SEQ;
    const size_t RS = 3 * EMB;
    const unsigned FULL = 0xffffffffu;

    // ---- load Q tile (scale by exact 0.125 in fp16) ----
    {
        const int r = tid >> 1, c0 = (tid & 1) * 32;
        const __half* qp = qkv + (tb + q0 + r) * RS + hh * HD + c0;
        const __half2 sc2 = __floats2half2_rn(0.125f, 0.125f);
#pragma unroll
        for (int j = 0; j < 4; ++j) {
            uint4 raw = *(const uint4*)(qp + j * 8);
            __half2* hp = (__half2*)&raw;
#pragma unroll
            for (int e = 0; e < 4; ++e) hp[e] = __hmul2(hp[e], sc2);
            sts128(Qb + sw128((uint32_t)(r * 128 + (c0 + j * 8) * 2)), raw);
        }
    }
    __syncthreads();

    uint32_t QF[2][4][4];
    {
        const int g = lane >> 3;
#pragma unroll
        for (int mt = 0; mt < 2; ++mt)
#pragma unroll
            for (int t = 0; t < 4; ++t) {
                const int r = mg * 32 + mt * 16 + (g & 1) * 8 + (lane & 7);
                const int cb = t * 32 + (g >> 1) * 16;
                ldsm_x4(Qb + sw128((uint32_t)(r * 128 + cb)), QF[mt][t]);
            }
    }

    float Oa[2][8][4];
#pragma unroll
    for (int mt = 0; mt < 2; ++mt)
#pragma unroll
        for (int nt = 0; nt < 8; ++nt)
#pragma unroll
            for (int c = 0; c < 4; ++c) Oa[mt][nt][c] = 0.f;
    float m_run[4], l_run[4];
#pragma unroll
    for (int ri = 0; ri < 4; ++ri) { m_run[ri] = -INFINITY; l_run[ri] = 0.f; }

    for (int kt = 0; kt < SEQ / 128; ++kt) {
        __syncthreads();
        {
            const int r = tid >> 1, c0 = (tid & 1) * 32;
            const __half* kp = qkv + (tb + kt * 128 + r) * RS + EMB + hh * HD + c0;
            const __half* vp = kp + EMB;
#pragma unroll
            for (int j = 0; j < 4; ++j) {
                uint32_t off = sw128((uint32_t)(r * 128 + (c0 + j * 8) * 2));
                sts128(Kb + off, *(const uint4*)(kp + j * 8));
                sts128(Vb + off, *(const uint4*)(vp + j * 8));
            }
        }
        __syncthreads();

        float sacc[2][8][4];
#pragma unroll
        for (int mt = 0; mt < 2; ++mt)
#pragma unroll
            for (int nt = 0; nt < 8; ++nt)
#pragma unroll
                for (int c = 0; c < 4; ++c) sacc[mt][nt][c] = 0.f;

        const int g = lane >> 3;
#pragma unroll
        for (int t = 0; t < 4; ++t) {
#pragma unroll
            for (int pr = 0; pr < 4; ++pr) {
                const int r = kh * 64 + pr * 16 + (g >> 1) * 8 + (lane & 7);
                const int cb = t * 32 + (g & 1) * 16;
                uint32_t tt[4];
                ldsm_x4(Kb + sw128((uint32_t)(r * 128 + cb)), tt);
#pragma unroll
                for (int mt = 0; mt < 2; ++mt) {
                    mma16816(sacc[mt][pr * 2 + 0], QF[mt][t], tt);
                    mma16816(sacc[mt][pr * 2 + 1], QF[mt][t], tt + 2);
                }
            }
        }

        float mloc[4];
#pragma unroll
        for (int ri = 0; ri < 4; ++ri) {
            const int mt = ri >> 1, h = ri & 1;
            float mx = sacc[mt][0][h * 2];
#pragma unroll
            for (int nt = 0; nt < 8; ++nt) {
                mx = fmaxf(mx, sacc[mt][nt][h * 2]);
                mx = fmaxf(mx, sacc[mt][nt][h * 2 + 1]);
            }
            mx = fmaxf(mx, __shfl_xor_sync(FULL, mx, 1));
            mx = fmaxf(mx, __shfl_xor_sync(FULL, mx, 2));
            mloc[ri] = mx;
        }
        if ((lane & 3) == 0) {
#pragma unroll
            for (int ri = 0; ri < 4; ++ri) {
                const int row = mg * 32 + (ri >> 1) * 16 + (ri & 1) * 8 + (lane >> 2);
                smax[kh][row] = mloc[ri];
            }
        }
        __syncthreads();

        float fexp[4];
#pragma unroll
        for (int ri = 0; ri < 4; ++ri) {
            const int row = mg * 32 + (ri >> 1) * 16 + (ri & 1) * 8 + (lane >> 2);
            const float mk = fmaxf(smax[0][row], smax[1][row]);
            const float mn = fmaxf(m_run[ri], mk);
            fexp[ri] = __expf(m_run[ri] - mn);
            m_run[ri] = mn;
            l_run[ri] *= fexp[ri];
        }
#pragma unroll
        for (int mt = 0; mt < 2; ++mt)
#pragma unroll
            for (int nt = 0; nt < 8; ++nt)
#pragma unroll
                for (int c = 0; c < 4; ++c) {
                    const int ri = mt * 2 + (c >> 1);
                    float p = __expf(sacc[mt][nt][c] - m_run[ri]);
                    sacc[mt][nt][c] = p;
                    l_run[ri] += p;
                }
#pragma unroll
        for (int mt = 0; mt < 2; ++mt)
#pragma unroll
            for (int nt = 0; nt < 8; ++nt)
#pragma unroll
                for (int c = 0; c < 4; ++c)
                    Oa[mt][nt][c] *= fexp[mt * 2 + (c >> 1)];

#pragma unroll
        for (int k2 = 0; k2 < 4; ++k2) {
            uint32_t pa[2][4];
#pragma unroll
            for (int mt = 0; mt < 2; ++mt) {
                pa[mt][0] = h2u(__floats2half2_rn(sacc[mt][2 * k2][0],     sacc[mt][2 * k2][1]));
                pa[mt][1] = h2u(__floats2half2_rn(sacc[mt][2 * k2][2],     sacc[mt][2 * k2][3]));
                pa[mt][2] = h2u(__floats2half2_rn(sacc[mt][2 * k2 + 1][0], sacc[mt][2 * k2 + 1][1]));
                pa[mt][3] = h2u(__floats2half2_rn(sacc[mt][2 * k2 + 1][2], sacc[mt][2 * k2 + 1][3]));
            }
#pragma unroll
            for (int npr = 0; npr < 4; ++npr) {
                const int r = kh * 64 + k2 * 16 + (g & 1) * 8 + (lane & 7);
                const int cb = npr * 32 + (g >> 1) * 16;
                uint32_t tt[4];
                ldsm_x4_t(Vb + sw128((uint32_t)(r * 128 + cb)), tt);
#pragma unroll
                for (int mt = 0; mt < 2; ++mt) {
                    mma16816(Oa[mt][npr * 2 + 0], pa[mt], tt);
                    mma16816(Oa[mt][npr * 2 + 1], pa[mt], tt + 2);
                }
            }
        }
    }

#pragma unroll
    for (int ri = 0; ri < 4; ++ri) {
        l_run[ri] += __shfl_xor_sync(FULL, l_run[ri], 1);
        l_run[ri] += __shfl_xor_sync(FULL, l_run[ri], 2);
    }
    if ((lane & 3) == 0) {
#pragma unroll
        for (int ri = 0; ri < 4; ++ri) {
            const int row = mg * 32 + (ri >> 1) * 16 + (ri & 1) * 8 + (lane >> 2);
            lsum2[kh][row] = l_run[ri];
        }
    }
    __syncthreads();

    if (kh == 0) {
#pragma unroll
        for (int mt = 0; mt < 2; ++mt)
#pragma unroll
            for (int nt = 0; nt < 8; ++nt)
#pragma unroll
                for (int h = 0; h < 2; ++h) {
                    const int row = mg * 32 + mt * 16 + h * 8 + (lane >> 2);
                    const int col = nt * 8 + (lane & 3) * 2;
                    float2 v; v.x = Oa[mt][nt][h * 2]; v.y = Oa[mt][nt][h * 2 + 1];
                    *(float2*)&Obuf[row * 68 + col] = v;
                }
    }
    __syncthreads();
    if (kh == 1) {
#pragma unroll
        for (int mt = 0; mt < 2; ++mt)
#pragma unroll
            for (int h = 0; h < 2; ++h) {
                const int row = mg * 32 + mt * 16 + h * 8 + (lane >> 2);
                const float inv = 1.f / (lsum2[0][row] + lsum2[1][row]);
#pragma unroll
                for (int nt = 0; nt < 8; ++nt) {
                    const int col = nt * 8 + (lane & 3) * 2;
                    const float2 pv = *(const float2*)&Obuf[row * 68 + col];
                    *(__half2*)(o + (tb + q0 + row) * EMB + hh * HD + col) =
                        __floats2half2_rn((Oa[mt][nt][h * 2 + 0] + pv.x) * inv,
                                          (Oa[mt][nt][h * 2 + 1] + pv.y) * inv);
                }
            }
    }
}

// ---------------- LayerNorm: fp32 in -> fp16 out ----------------
__global__ void ln_kernel(const float* __restrict__ in, __half* __restrict__ out,
                          const float* __restrict__ gam, const float* __restrict__ bet)
{
    __shared__ float red[8], red2[8];
    __shared__ float s_mu, s_rstd;
    const int row = blockIdx.x;
    const float* x = in + (size_t)row * EMB;
    __half* y = out + (size_t)row * EMB;
    const int tid = threadIdx.x;

    float4 v = *(const float4*)(x + tid * 4);
    float s  = v.x + v.y + v.z + v.w;
    float sq = v.x * v.x + v.y * v.y + v.z * v.z + v.w * v.w;
    const unsigned FULL = 0xffffffffu;
#pragma unroll
    for (int o = 16; o > 0; o >>= 1) {
        s  += __shfl_down_sync(FULL, s, o);
        sq += __shfl_down_sync(FULL, sq, o);
    }
    int warp = tid >> 5, lane = tid & 31;
    if (lane == 0) { red[warp] = s; red2[warp] = sq; }
    __syncthreads();
    if (warp == 0) {
        s  = (lane < 8) ? red[lane]  : 0.f;
        sq = (lane < 8) ? red2[lane] : 0.f;
#pragma unroll
        for (int o = 4; o > 0; o >>= 1) {
            s  += __shfl_down_sync(FULL, s, o);
            sq += __shfl_down_sync(FULL, sq, o);
        }
        if (lane == 0) {
            float mu = s * (1.f / EMB);
            float var = sq * (1.f / EMB) - mu * mu;
            s_mu = mu; s_rstd = rsqrtf(var + LN_EPS);
        }
    }
    __syncthreads();
    const float mu = s_mu, rstd = s_rstd;
    const float4 g4 = *(const float4*)(gam + tid * 4);
    const float4 b4 = *(const float4*)(bet + tid * 4);
    __half2 h0 = __floats2half2_rn((v.x - mu) * rstd * g4.x + b4.x,
                                   (v.y - mu) * rstd * g4.y + b4.y);
    __half2 h1 = __floats2half2_rn((v.z - mu) * rstd * g4.z + b4.z,
                                   (v.w - mu) * rstd * g4.w + b4.w);
    uint2 pk; pk.x = h2u(h0); pk.y = h2u(h1);
    *(uint2*)(y + tid * 4) = pk;
}

// ---------------- launch ----------------
extern "C" void kernel_launch(void* const* d_in, const int* in_sizes, int n_in,
                              void* d_out, int out_size)
{
    const float* x      = (const float*)d_in[0];
    const float* ln1_g  = (const float*)d_in[1];
    const float* ln1_b  = (const float*)d_in[2];
    const float* ln2_g  = (const float*)d_in[3];
    const float* ln2_b  = (const float*)d_in[4];
    const float* w_qkv  = (const float*)d_in[5];
    const float* b_qkv  = (const float*)d_in[6];
    const float* w_proj = (const float*)d_in[7];
    const float* b_proj = (const float*)d_in[8];
    const float* w_fc1  = (const float*)d_in[9];
    const float* b_fc1  = (const float*)d_in[10];
    const float* w_fc2  = (const float*)d_in[11];
    const float* b_fc2  = (const float*)d_in[12];
    float* out = (float*)d_out;

    void *p_h16, *p_qkv16, *p_o16, *p_act16, *p_x1;
    void *p_wq, *p_wp, *p_w1, *p_w2;
    cudaGetSymbolAddress(&p_h16, g_h16);
    cudaGetSymbolAddress(&p_qkv16, g_qkv16);
    cudaGetSymbolAddress(&p_o16, g_o16);
    cudaGetSymbolAddress(&p_act16, g_act16);
    cudaGetSymbolAddress(&p_x1, g_x1);
    cudaGetSymbolAddress(&p_wq, g_wq16);
    cudaGetSymbolAddress(&p_wp, g_wp16);
    cudaGetSymbolAddress(&p_w1, g_w116);
    cudaGetSymbolAddress(&p_w2, g_w216);
    __half* h16   = (__half*)p_h16;
    __half* qkv16 = (__half*)p_qkv16;
    __half* o16   = (__half*)p_o16;
    __half* act16 = (__half*)p_act16;
    float*  x1    = (float*)p_x1;
    __half* wq16  = (__half*)p_wq;
    __half* wp16  = (__half*)p_wp;
    __half* w116  = (__half*)p_w1;
    __half* w216  = (__half*)p_w2;

    cudaFuncSetAttribute(hgemm<0>, cudaFuncAttributeMaxDynamicSharedMemorySize, GEMM_SMEM);
    cudaFuncSetAttribute(hgemm<1>, cudaFuncAttributeMaxDynamicSharedMemorySize, GEMM_SMEM);
    cudaFuncSetAttribute(hgemm<2>, cudaFuncAttributeMaxDynamicSharedMemorySize, GEMM_SMEM);
    cudaFuncSetAttribute(attn_mma, cudaFuncAttributeMaxDynamicSharedMemorySize, ATT_SMEM);

    // 0. weight conversion (fp32 -> fp16)
    f2h_kernel<<<(EMB * 3 * EMB) / (8 * 256), 256>>>(w_qkv, wq16, EMB * 3 * EMB);
    f2h_kernel<<<(EMB * EMB) / (8 * 256), 256>>>(w_proj, wp16, EMB * EMB);
    f2h_kernel<<<(EMB * MLP) / (8 * 256), 256>>>(w_fc1, w116, EMB * MLP);
    f2h_kernel<<<(MLP * EMB) / (8 * 256), 256>>>(w_fc2, w216, MLP * EMB);

    // 1. LN1 -> h16
    ln_kernel<<<TOK, 256>>>(x, h16, ln1_g, ln1_b);
    // 2. QKV (fp16 out)
    hgemm<0><<<dim3(3 * EMB / 128, TOK / 128), 256, GEMM_SMEM>>>(
        h16, wq16, b_qkv, nullptr, qkv16, TOK, 3 * EMB, EMB);
    // 3. attention (fp16 in/out)
    attn_mma<<<dim3(2 * NH, SEQ / 128), 256, ATT_SMEM>>>(qkv16, o16);
    // 4. proj + residual (fp32 out)
    hgemm<2><<<dim3(EMB / 128, TOK / 128), 256, GEMM_SMEM>>>(
        o16, wp16, b_proj, x, x1, TOK, EMB, EMB);
    // 5. LN2 -> h16
    ln_kernel<<<TOK, 256>>>(x1, h16, ln2_g, ln2_b);
    // 6. FC1 + GELU (fp16 out)
    hgemm<1><<<dim3(MLP / 128, TOK / 128), 256, GEMM_SMEM>>>(
        h16, w116, b_fc1, nullptr, act16, TOK, MLP, EMB);
    // 7. FC2 + residual (fp32 out)
    hgemm<2><<<dim3(EMB / 128, TOK / 128), 256, GEMM_SMEM>>>(
        act16, w216, b_fc2, x1, out, TOK, EMB, MLP);
}

// round 8
// speedup vs baseline: 23.4779x; 1.0568x over previous
#include <cuda_runtime.h>
#include <cuda_fp16.h>
#include <math.h>
#include <stdint.h>

// ---------------- problem constants ----------------
#define TOK   4096
#define EMB   1024
#define NH    16
#define HD    64
#define SEQ   2048
#define MLP   4096
#define LN_EPS 1e-5f

// ---------------- scratch ----------------
static __device__ __half g_h16 [(size_t)TOK * EMB];
static __device__ __half g_qkv16[(size_t)TOK * 3 * EMB];
static __device__ __half g_o16 [(size_t)TOK * EMB];
static __device__ __half g_act16[(size_t)TOK * MLP];
static __device__ float  g_x1  [(size_t)TOK * EMB];
static __device__ __half g_wq16[(size_t)EMB * 3 * EMB];
static __device__ __half g_wp16[(size_t)EMB * EMB];
static __device__ __half g_w116[(size_t)EMB * MLP];
static __device__ __half g_w216[(size_t)MLP * EMB];

// ---------------- helpers ----------------
__device__ __forceinline__ uint32_t smem_u32(const void* p) {
    uint32_t a;
    asm("{ .reg .u64 t; cvta.to.shared.u64 t, %1; cvt.u32.u64 %0, t; }" : "=r"(a) : "l"(p));
    return a;
}
__device__ __forceinline__ void sts128(uint32_t addr, uint4 v) {
    asm volatile("st.shared.v4.b32 [%0], {%1, %2, %3, %4};"
        :: "r"(addr), "r"(v.x), "r"(v.y), "r"(v.z), "r"(v.w));
}
__device__ __forceinline__ uint32_t h2u(__half2 h) { return *(uint32_t*)&h; }
// 64B rows: 16B chunk bits [4:6) ^= (row>>1)&3
__device__ __forceinline__ uint32_t swz(uint32_t off) {
    return off ^ (((off >> 7) & 3u) << 4);
}
// 128B rows: 16B chunk bits [4:7) ^= row&7
__device__ __forceinline__ uint32_t sw128(uint32_t off) {
    return off ^ ((off >> 3) & 0x70u);
}
// 256B rows: 16B chunk bits [4:7) ^= row&7
__device__ __forceinline__ uint32_t sw256(uint32_t off) {
    return off ^ (((off >> 8) & 7u) << 4);
}
__device__ __forceinline__ void ldsm_x4(uint32_t addr, uint32_t* r) {
    asm volatile("ldmatrix.sync.aligned.m8n8.x4.shared.b16 {%0,%1,%2,%3}, [%4];"
        : "=r"(r[0]), "=r"(r[1]), "=r"(r[2]), "=r"(r[3]) : "r"(addr));
}
__device__ __forceinline__ void ldsm_x4_t(uint32_t addr, uint32_t* r) {
    asm volatile("ldmatrix.sync.aligned.m8n8.x4.trans.shared.b16 {%0,%1,%2,%3}, [%4];"
        : "=r"(r[0]), "=r"(r[1]), "=r"(r[2]), "=r"(r[3]) : "r"(addr));
}
__device__ __forceinline__ void mma16816(float* d, const uint32_t* a, const uint32_t* b) {
    asm volatile("mma.sync.aligned.m16n8k16.row.col.f32.f16.f16.f32 "
        "{%0,%1,%2,%3}, {%4,%5,%6,%7}, {%8,%9}, {%0,%1,%2,%3};"
        : "+f"(d[0]), "+f"(d[1]), "+f"(d[2]), "+f"(d[3])
        : "r"(a[0]), "r"(a[1]), "r"(a[2]), "r"(a[3]), "r"(b[0]), "r"(b[1]));
}
__device__ __forceinline__ void cpasync16(uint32_t saddr, const void* g) {
    asm volatile("cp.async.cg.shared.global [%0], [%1], 16;" :: "r"(saddr), "l"(g));
}
#define CP_COMMIT() asm volatile("cp.async.commit_group;" ::: "memory")
#define CP_WAIT2()  asm volatile("cp.async.wait_group 2;" ::: "memory")
#define CP_WAIT1()  asm volatile("cp.async.wait_group 1;" ::: "memory")
__device__ __forceinline__ float gelu_exact(float x) {
    return 0.5f * x * (1.f + erff(x * 0.70710678118654752f));
}

// =====================================================================
// fp32 -> fp16 weight conversion (single launch, all 4 weights)
// segments (blocks of 2048 elems): wq 1536 | wp 512 | w1 2048 | w2 2048
// =====================================================================
__global__ void f2h_all(const float* __restrict__ wq, __half* __restrict__ dq,
                        const float* __restrict__ wp, __half* __restrict__ dp,
                        const float* __restrict__ w1, __half* __restrict__ d1,
                        const float* __restrict__ w2, __half* __restrict__ d2)
{
    const int b = blockIdx.x;
    const float* src; __half* dst; int rb;
    if (b < 1536)      { src = wq; dst = dq; rb = b; }
    else if (b < 2048) { src = wp; dst = dp; rb = b - 1536; }
    else if (b < 4096) { src = w1; dst = d1; rb = b - 2048; }
    else               { src = w2; dst = d2; rb = b - 4096; }
    const int i = (rb * 256 + threadIdx.x) * 8;
    float4 a = *(const float4*)(src + i);
    float4 c = *(const float4*)(src + i + 4);
    uint4 o;
    o.x = h2u(__floats2half2_rn(a.x, a.y));
    o.y = h2u(__floats2half2_rn(a.z, a.w));
    o.z = h2u(__floats2half2_rn(c.x, c.y));
    o.w = h2u(__floats2half2_rn(c.z, c.w));
    *(uint4*)(dst + i) = o;
}

// =====================================================================
// HMMA GEMM, all-fp16 operands, cp.async 4-stage pipeline. (unchanged R7)
// Block 128x128, BK=32, 8 warps (2M x 4N) of 64x32.
// MODE: 0 = bias -> fp16 out, 1 = bias+gelu -> fp16 out, 2 = bias+res -> fp32 out
// =====================================================================
#define GEMM_SMEM (4 * 16384)

template<int MODE>
__global__ void __launch_bounds__(256, 2)
hgemm(const __half* __restrict__ A, const __half* __restrict__ B,
      const float* __restrict__ bias, const float* __restrict__ res,
      void* __restrict__ Cout, int M, int N, int K)
{
    extern __shared__ char dsm[];
    const uint32_t base = smem_u32(dsm);

    const int tid  = threadIdx.x;
    const int lane = tid & 31, wid = tid >> 5;
    const int wm = (wid & 1) * 64;
    const int wn = (wid >> 1) * 32;
    const int bm = blockIdx.y * 128, bn = blockIdx.x * 128;
    const int g = lane >> 3;

    float acc[4][4][4];
#pragma unroll
    for (int i = 0; i < 4; ++i)
#pragma unroll
        for (int j = 0; j < 4; ++j)
#pragma unroll
            for (int c = 0; c < 4; ++c) acc[i][j][c] = 0.f;

    const int nch = K / 32;

    auto issue = [&](int buf, int kc) {
        const uint32_t sA = base + buf * 16384u;
        const uint32_t sB = sA + 8192u;
#pragma unroll
        for (int i = 0; i < 2; ++i) {
            const int cc = tid * 2 + i;
            const int rowa = cc >> 2, kch = cc & 3;
            cpasync16(sA + swz((uint32_t)(rowa * 64 + kch * 16)),
                      A + (size_t)(bm + rowa) * K + kc * 32 + kch * 8);
            const int rowb = cc >> 4, nch2 = cc & 15;
            cpasync16(sB + sw256((uint32_t)(rowb * 256 + nch2 * 16)),
                      B + (size_t)(kc * 32 + rowb) * N + bn + nch2 * 8);
        }
    };

    auto compute = [&](int buf) {
        const uint32_t sA = base + buf * 16384u;
        const uint32_t sB = sA + 8192u;
#pragma unroll
        for (int ks = 0; ks < 2; ++ks) {
            uint32_t AF[4][4];
            const int ra = wm + (g & 1) * 8 + (lane & 7);
            const int ca = ks * 32 + (g >> 1) * 16;
#pragma unroll
            for (int mt = 0; mt < 4; ++mt)
                ldsm_x4(sA + swz((uint32_t)((ra + mt * 16) * 64 + ca)), AF[mt]);
            const int rb = ks * 16 + (g & 1) * 8 + (lane & 7);
#pragma unroll
            for (int p = 0; p < 2; ++p) {
                uint32_t t[4];
                const int cbb = (wn + p * 16) * 2 + (g >> 1) * 16;
                ldsm_x4_t(sB + sw256((uint32_t)(rb * 256 + cbb)), t);
#pragma unroll
                for (int mt = 0; mt < 4; ++mt) {
                    mma16816(acc[mt][p * 2 + 0], AF[mt], t);
                    mma16816(acc[mt][p * 2 + 1], AF[mt], t + 2);
                }
            }
        }
    };

    issue(0, 0); CP_COMMIT();
    issue(1, 1); CP_COMMIT();
    issue(2, 2); CP_COMMIT();

    for (int kc = 0; kc < nch; ++kc) {
        CP_WAIT2();
        __syncthreads();
        compute(kc & 3);
        if (kc + 3 < nch) issue((kc + 3) & 3, kc + 3);
        CP_COMMIT();
    }

#pragma unroll
    for (int mt = 0; mt < 4; ++mt) {
#pragma unroll
        for (int nt = 0; nt < 4; ++nt) {
            const int col = bn + wn + nt * 8 + (lane & 3) * 2;
            const float b0 = bias[col], b1 = bias[col + 1];
#pragma unroll
            for (int dp = 0; dp < 2; ++dp) {
                const int row = bm + wm + mt * 16 + (lane >> 2) + dp * 8;
                float o0 = acc[mt][nt][dp * 2 + 0] + b0;
                float o1 = acc[mt][nt][dp * 2 + 1] + b1;
                if (MODE == 1) { o0 = gelu_exact(o0); o1 = gelu_exact(o1); }
                if (MODE == 2) {
                    const float2 rv = *(const float2*)(res + (size_t)row * N + col);
                    float2 ov; ov.x = o0 + rv.x; ov.y = o1 + rv.y;
                    *(float2*)((float*)Cout + (size_t)row * N + col) = ov;
                } else {
                    *(__half2*)((__half*)Cout + (size_t)row * N + col) =
                        __floats2half2_rn(o0, o1);
                }
            }
        }
    }
}

// =====================================================================
// HMMA flash attention, fp16 in/out, cp.async double-buffered K/V.
// CTA = (b, head) x 128 queries, 256 threads; 8 warps (4 q-groups x 2 key-halves).
// smem: Q 16KB | 2 x (K 16KB + V 16KB) stages; Obuf fp32 aliases stage 0.
// =====================================================================
#define ATT_SMEM (16384 + 2 * 32768)

__global__ void __launch_bounds__(256, 1)
attn_mma(const __half* __restrict__ qkv, __half* __restrict__ o)
{
    extern __shared__ char dynsm[];
    __shared__ float smax[2][128];
    __shared__ float lsum2[2][128];

    const uint32_t Qb = smem_u32(dynsm);
    float* Obuf = (float*)(dynsm + 16384);   // aliases stage 0 after last compute

    const int tid  = threadIdx.x;
    const int lane = tid & 31, wid = tid >> 5;
    const int mg = wid >> 1, kh = wid & 1;
    const int b = blockIdx.x >> 4, hh = blockIdx.x & 15;
    const int q0 = blockIdx.y * 128;
    const size_t tb = (size_t)b * SEQ;
    const size_t RS = 3 * EMB;
    const unsigned FULL = 0xffffffffu;

    // ---- issue K/V tile kt into stage s (cp.async) ----
    auto issueKV = [&](int s, int kt) {
        const uint32_t Kb = Qb + 16384u + (uint32_t)s * 32768u;
        const uint32_t Vb = Kb + 16384u;
        const __half* kbase = qkv + (tb + kt * 128) * RS + EMB + hh * HD;
#pragma unroll
        for (int i = 0; i < 4; ++i) {
            const int cc = tid * 4 + i;          // 0..1023
            const int r = cc >> 3, ch = cc & 7;
            const uint32_t off = sw128((uint32_t)(r * 128 + ch * 16));
            cpasync16(Kb + off, kbase + (size_t)r * RS + ch * 8);
            cpasync16(Vb + off, kbase + EMB + (size_t)r * RS + ch * 8);
        }
    };

    // ---- load Q tile (scale by exact 0.125 in fp16) ----
    {
        const int r = tid >> 1, c0 = (tid & 1) * 32;
        const __half* qp = qkv + (tb + q0 + r) * RS + hh * HD + c0;
        const __half2 sc2 = __floats2half2_rn(0.125f, 0.125f);
#pragma unroll
        for (int j = 0; j < 4; ++j) {
            uint4 raw = *(const uint4*)(qp + j * 8);
            __half2* hp = (__half2*)&raw;
#pragma unroll
            for (int e = 0; e < 4; ++e) hp[e] = __hmul2(hp[e], sc2);
            sts128(Qb + sw128((uint32_t)(r * 128 + (c0 + j * 8) * 2)), raw);
        }
    }
    issueKV(0, 0); CP_COMMIT();
    __syncthreads();

    uint32_t QF[2][4][4];
    {
        const int g = lane >> 3;
#pragma unroll
        for (int mt = 0; mt < 2; ++mt)
#pragma unroll
            for (int t = 0; t < 4; ++t) {
                const int r = mg * 32 + mt * 16 + (g & 1) * 8 + (lane & 7);
                const int cb = t * 32 + (g >> 1) * 16;
                ldsm_x4(Qb + sw128((uint32_t)(r * 128 + cb)), QF[mt][t]);
            }
    }

    float Oa[2][8][4];
#pragma unroll
    for (int mt = 0; mt < 2; ++mt)
#pragma unroll
        for (int nt = 0; nt < 8; ++nt)
#pragma unroll
            for (int c = 0; c < 4; ++c) Oa[mt][nt][c] = 0.f;
    float m_run[4], l_run[4];
#pragma unroll
    for (int ri = 0; ri < 4; ++ri) { m_run[ri] = -INFINITY; l_run[ri] = 0.f; }

    for (int kt = 0; kt < SEQ / 128; ++kt) {
        __syncthreads();                          // prev compute done -> safe to overwrite
        if (kt + 1 < SEQ / 128) issueKV((kt + 1) & 1, kt + 1);
        CP_COMMIT();
        CP_WAIT1();                               // stage kt&1 complete
        __syncthreads();

        const uint32_t Kb = Qb + 16384u + (uint32_t)(kt & 1) * 32768u;
        const uint32_t Vb = Kb + 16384u;

        float sacc[2][8][4];
#pragma unroll
        for (int mt = 0; mt < 2; ++mt)
#pragma unroll
            for (int nt = 0; nt < 8; ++nt)
#pragma unroll
                for (int c = 0; c < 4; ++c) sacc[mt][nt][c] = 0.f;

        const int g = lane >> 3;
#pragma unroll
        for (int t = 0; t < 4; ++t) {
#pragma unroll
            for (int pr = 0; pr < 4; ++pr) {
                const int r = kh * 64 + pr * 16 + (g >> 1) * 8 + (lane & 7);
                const int cb = t * 32 + (g & 1) * 16;
                uint32_t tt[4];
                ldsm_x4(Kb + sw128((uint32_t)(r * 128 + cb)), tt);
#pragma unroll
                for (int mt = 0; mt < 2; ++mt) {
                    mma16816(sacc[mt][pr * 2 + 0], QF[mt][t], tt);
                    mma16816(sacc[mt][pr * 2 + 1], QF[mt][t], tt + 2);
                }
            }
        }

        float mloc[4];
#pragma unroll
        for (int ri = 0; ri < 4; ++ri) {
            const int mt = ri >> 1, h = ri & 1;
            float mx = sacc[mt][0][h * 2];
#pragma unroll
            for (int nt = 0; nt < 8; ++nt) {
                mx = fmaxf(mx, sacc[mt][nt][h * 2]);
                mx = fmaxf(mx, sacc[mt][nt][h * 2 + 1]);
            }
            mx = fmaxf(mx, __shfl_xor_sync(FULL, mx, 1));
            mx = fmaxf(mx, __shfl_xor_sync(FULL, mx, 2));
            mloc[ri] = mx;
        }
        if ((lane & 3) == 0) {
#pragma unroll
            for (int ri = 0; ri < 4; ++ri) {
                const int row = mg * 32 + (ri >> 1) * 16 + (ri & 1) * 8 + (lane >> 2);
                smax[kh][row] = mloc[ri];
            }
        }
        __syncthreads();

        float fexp[4];
#pragma unroll
        for (int ri = 0; ri < 4; ++ri) {
            const int row = mg * 32 + (ri >> 1) * 16 + (ri & 1) * 8 + (lane >> 2);
            const float mk = fmaxf(smax[0][row], smax[1][row]);
            const float mn = fmaxf(m_run[ri], mk);
            fexp[ri] = __expf(m_run[ri] - mn);
            m_run[ri] = mn;
            l_run[ri] *= fexp[ri];
        }
#pragma unroll
        for (int mt = 0; mt < 2; ++mt)
#pragma unroll
            for (int nt = 0; nt < 8; ++nt)
#pragma unroll
                for (int c = 0; c < 4; ++c) {
                    const int ri = mt * 2 + (c >> 1);
                    float p = __expf(sacc[mt][nt][c] - m_run[ri]);
                    sacc[mt][nt][c] = p;
                    l_run[ri] += p;
                }
#pragma unroll
        for (int mt = 0; mt < 2; ++mt)
#pragma unroll
            for (int nt = 0; nt < 8; ++nt)
#pragma unroll
                for (int c = 0; c < 4; ++c)
                    Oa[mt][nt][c] *= fexp[mt * 2 + (c >> 1)];

#pragma unroll
        for (int k2 = 0; k2 < 4; ++k2) {
            uint32_t pa[2][4];
#pragma unroll
            for (int mt = 0; mt < 2; ++mt) {
                pa[mt][0] = h2u(__floats2half2_rn(sacc[mt][2 * k2][0],     sacc[mt][2 * k2][1]));
                pa[mt][1] = h2u(__floats2half2_rn(sacc[mt][2 * k2][2],     sacc[mt][2 * k2][3]));
                pa[mt][2] = h2u(__floats2half2_rn(sacc[mt][2 * k2 + 1][0], sacc[mt][2 * k2 + 1][1]));
                pa[mt][3] = h2u(__floats2half2_rn(sacc[mt][2 * k2 + 1][2], sacc[mt][2 * k2 + 1][3]));
            }
#pragma unroll
            for (int npr = 0; npr < 4; ++npr) {
                const int r = kh * 64 + k2 * 16 + (g & 1) * 8 + (lane & 7);
                const int cb = npr * 32 + (g >> 1) * 16;
                uint32_t tt[4];
                ldsm_x4_t(Vb + sw128((uint32_t)(r * 128 + cb)), tt);
#pragma unroll
                for (int mt = 0; mt < 2; ++mt) {
                    mma16816(Oa[mt][npr * 2 + 0], pa[mt], tt);
                    mma16816(Oa[mt][npr * 2 + 1], pa[mt], tt + 2);
                }
            }
        }
    }

#pragma unroll
    for (int ri = 0; ri < 4; ++ri) {
        l_run[ri] += __shfl_xor_sync(FULL, l_run[ri], 1);
        l_run[ri] += __shfl_xor_sync(FULL, l_run[ri], 2);
    }
    if ((lane & 3) == 0) {
#pragma unroll
        for (int ri = 0; ri < 4; ++ri) {
            const int row = mg * 32 + (ri >> 1) * 16 + (ri & 1) * 8 + (lane >> 2);
            lsum2[kh][row] = l_run[ri];
        }
    }
    __syncthreads();   // all V reads done; Obuf may alias stage 0

    if (kh == 0) {
#pragma unroll
        for (int mt = 0; mt < 2; ++mt)
#pragma unroll
            for (int nt = 0; nt < 8; ++nt)
#pragma unroll
                for (int h = 0; h < 2; ++h) {
                    const int row = mg * 32 + mt * 16 + h * 8 + (lane >> 2);
                    const int col = nt * 8 + (lane & 3) * 2;
                    float2 v; v.x = Oa[mt][nt][h * 2]; v.y = Oa[mt][nt][h * 2 + 1];
                    *(float2*)&Obuf[row * 68 + col] = v;
                }
    }
    __syncthreads();
    if (kh == 1) {
#pragma unroll
        for (int mt = 0; mt < 2; ++mt)
#pragma unroll
            for (int h = 0; h < 2; ++h) {
                const int row = mg * 32 + mt * 16 + h * 8 + (lane >> 2);
                const float inv = 1.f / (lsum2[0][row] + lsum2[1][row]);
#pragma unroll
                for (int nt = 0; nt < 8; ++nt) {
                    const int col = nt * 8 + (lane & 3) * 2;
                    const float2 pv = *(const float2*)&Obuf[row * 68 + col];
                    *(__half2*)(o + (tb + q0 + row) * EMB + hh * HD + col) =
                        __floats2half2_rn((Oa[mt][nt][h * 2 + 0] + pv.x) * inv,
                                          (Oa[mt][nt][h * 2 + 1] + pv.y) * inv);
                }
            }
    }
}

// ---------------- LayerNorm: fp32 in -> fp16 out ----------------
__global__ void ln_kernel(const float* __restrict__ in, __half* __restrict__ out,
                          const float* __restrict__ gam, const float* __restrict__ bet)
{
    __shared__ float red[8], red2[8];
    __shared__ float s_mu, s_rstd;
    const int row = blockIdx.x;
    const float* x = in + (size_t)row * EMB;
    __half* y = out + (size_t)row * EMB;
    const int tid = threadIdx.x;

    float4 v = *(const float4*)(x + tid * 4);
    float s  = v.x + v.y + v.z + v.w;
    float sq = v.x * v.x + v.y * v.y + v.z * v.z + v.w * v.w;
    const unsigned FULL = 0xffffffffu;
#pragma unroll
    for (int o = 16; o > 0; o >>= 1) {
        s  += __shfl_down_sync(FULL, s, o);
        sq += __shfl_down_sync(FULL, sq, o);
    }
    int warp = tid >> 5, lane = tid & 31;
    if (lane == 0) { red[warp] = s; red2[warp] = sq; }
    __syncthreads();
    if (warp == 0) {
        s  = (lane < 8) ? red[lane]  : 0.f;
        sq = (lane < 8) ? red2[lane] : 0.f;
#pragma unroll
        for (int o = 4; o > 0; o >>= 1) {
            s  += __shfl_down_sync(FULL, s, o);
            sq += __shfl_down_sync(FULL, sq, o);
        }
        if (lane == 0) {
            float mu = s * (1.f / EMB);
            float var = sq * (1.f / EMB) - mu * mu;
            s_mu = mu; s_rstd = rsqrtf(var + LN_EPS);
        }
    }
    __syncthreads();
    const float mu = s_mu, rstd = s_rstd;
    const float4 g4 = *(const float4*)(gam + tid * 4);
    const float4 b4 = *(const float4*)(bet + tid * 4);
    __half2 h0 = __floats2half2_rn((v.x - mu) * rstd * g4.x + b4.x,
                                   (v.y - mu) * rstd * g4.y + b4.y);
    __half2 h1 = __floats2half2_rn((v.z - mu) * rstd * g4.z + b4.z,
                                   (v.w - mu) * rstd * g4.w + b4.w);
    uint2 pk; pk.x = h2u(h0); pk.y = h2u(h1);
    *(uint2*)(y + tid * 4) = pk;
}

// ---------------- launch ----------------
extern "C" void kernel_launch(void* const* d_in, const int* in_sizes, int n_in,
                              void* d_out, int out_size)
{
    const float* x      = (const float*)d_in[0];
    const float* ln1_g  = (const float*)d_in[1];
    const float* ln1_b  = (const float*)d_in[2];
    const float* ln2_g  = (const float*)d_in[3];
    const float* ln2_b  = (const float*)d_in[4];
    const float* w_qkv  = (const float*)d_in[5];
    const float* b_qkv  = (const float*)d_in[6];
    const float* w_proj = (const float*)d_in[7];
    const float* b_proj = (const float*)d_in[8];
    const float* w_fc1  = (const float*)d_in[9];
    const float* b_fc1  = (const float*)d_in[10];
    const float* w_fc2  = (const float*)d_in[11];
    const float* b_fc2  = (const float*)d_in[12];
    float* out = (float*)d_out;

    void *p_h16, *p_qkv16, *p_o16, *p_act16, *p_x1;
    void *p_wq, *p_wp, *p_w1, *p_w2;
    cudaGetSymbolAddress(&p_h16, g_h16);
    cudaGetSymbolAddress(&p_qkv16, g_qkv16);
    cudaGetSymbolAddress(&p_o16, g_o16);
    cudaGetSymbolAddress(&p_act16, g_act16);
    cudaGetSymbolAddress(&p_x1, g_x1);
    cudaGetSymbolAddress(&p_wq, g_wq16);
    cudaGetSymbolAddress(&p_wp, g_wp16);
    cudaGetSymbolAddress(&p_w1, g_w116);
    cudaGetSymbolAddress(&p_w2, g_w216);
    __half* h16   = (__half*)p_h16;
    __half* qkv16 = (__half*)p_qkv16;
    __half* o16   = (__half*)p_o16;
    __half* act16 = (__half*)p_act16;
    float*  x1    = (float*)p_x1;
    __half* wq16  = (__half*)p_wq;
    __half* wp16  = (__half*)p_wp;
    __half* w116  = (__half*)p_w1;
    __half* w216  = (__half*)p_w2;

    cudaFuncSetAttribute(hgemm<0>, cudaFuncAttributeMaxDynamicSharedMemorySize, GEMM_SMEM);
    cudaFuncSetAttribute(hgemm<1>, cudaFuncAttributeMaxDynamicSharedMemorySize, GEMM_SMEM);
    cudaFuncSetAttribute(hgemm<2>, cudaFuncAttributeMaxDynamicSharedMemorySize, GEMM_SMEM);
    cudaFuncSetAttribute(attn_mma, cudaFuncAttributeMaxDynamicSharedMemorySize, ATT_SMEM);

    // 0. weight conversion (fp32 -> fp16), one launch
    f2h_all<<<6144, 256>>>(w_qkv, wq16, w_proj, wp16, w_fc1, w116, w_fc2, w216);

    // 1. LN1 -> h16
    ln_kernel<<<TOK, 256>>>(x, h16, ln1_g, ln1_b);
    // 2. QKV (fp16 out)
    hgemm<0><<<dim3(3 * EMB / 128, TOK / 128), 256, GEMM_SMEM>>>(
        h16, wq16, b_qkv, nullptr, qkv16, TOK, 3 * EMB, EMB);
    // 3. attention (fp16 in/out)
    attn_mma<<<dim3(2 * NH, SEQ / 128), 256, ATT_SMEM>>>(qkv16, o16);
    // 4. proj + residual (fp32 out)
    hgemm<2><<<dim3(EMB / 128, TOK / 128), 256, GEMM_SMEM>>>(
        o16, wp16, b_proj, x, x1, TOK, EMB, EMB);
    // 5. LN2 -> h16
    ln_kernel<<<TOK, 256>>>(x1, h16, ln2_g, ln2_b);
    // 6. FC1 + GELU (fp16 out)
    hgemm<1><<<dim3(MLP / 128, TOK / 128), 256, GEMM_SMEM>>>(
        h16, w116, b_fc1, nullptr, act16, TOK, MLP, EMB);
    // 7. FC2 + residual (fp32 out)
    hgemm<2><<<dim3(EMB / 128, TOK / 128), 256, GEMM_SMEM>>>(
        act16, w216, b_fc2, x1, out, TOK, EMB, MLP);
}